// round 3
// baseline (speedup 1.0000x reference)
#include <cuda_runtime.h>
#include <math.h>

// ---------------------------------------------------------------------------
// Scratch (device globals; no allocation anywhere)
// ---------------------------------------------------------------------------
static __device__ float g_bufA[33554432];   // 134 MB
static __device__ float g_bufB[16777216];   //  67 MB
static __device__ int   g_idx[8192];
static __device__ float g_e2[1024];

__device__ __forceinline__ void fma4(float* acc, float a, float4 w) {
    acc[0] += a * w.x; acc[1] += a * w.y; acc[2] += a * w.z; acc[3] += a * w.w;
}

// ---------------------------------------------------------------------------
// Encoder conv: k=4, s=2, p=1, ReLU.  in NCHW, w OIHW.
// Block 256 thr = 8 warps x 4 couts (32 couts). Lane owns one output column,
// RPT=4 output rows. Input patch de-interleaved into even/odd column planes
// so all activation LDS are stride-1 conflict-free. Weight LDS are warp-
// broadcast (all lanes in a warp share the cout group).
// ---------------------------------------------------------------------------
template<int TW, int TH, int CK>
__global__ __launch_bounds__(256)
void conv_enc(const float* __restrict__ in, const float* __restrict__ w,
              const float* __restrict__ bias, float* __restrict__ out,
              int Cin, int Hin, int Win, int Cout)
{
    constexpr int RG  = 32 / TW;        // row groups per warp
    constexpr int RPT = TH / RG;        // output rows per thread (=4)
    constexpr int IR  = 2 * TH + 2;     // input patch rows
    constexpr int HC  = TW + 1;         // half-cols per parity plane
    constexpr int HCP = (TW == 16) ? 18 : 33;  // pitch (bank-conflict-free)
    constexpr int TC  = 2 * TW + 2;     // input patch cols

    __shared__ float ev_s[CK][IR][HCP];
    __shared__ float od_s[CK][IR][HCP];
    __shared__ __align__(16) float w_s[CK][16][32];

    const int Hout = Hin >> 1, Wout = Win >> 1;
    const int tiles_x = Wout / TW;
    const int tx = blockIdx.x % tiles_x;
    const int ty = blockIdx.x / tiles_x;
    const int oy0 = ty * TH, ox0 = tx * TW;
    const int co0 = blockIdx.y * 32;
    const int b   = blockIdx.z;

    const int tid  = threadIdx.x;
    const int cg   = tid >> 5;               // warp = cout group
    const int lane = tid & 31;
    const int colx = lane % TW;
    const int rg   = lane / TW;
    const int cg4  = cg * 4;
    const int rbase = 2 * rg * RPT;

    float acc[RPT][4];
    #pragma unroll
    for (int i = 0; i < RPT; i++)
        #pragma unroll
        for (int c = 0; c < 4; c++) acc[i][c] = 0.f;

    const int  iy_org = 2 * oy0 - 1;
    const int  ix_org = 2 * ox0 - 1;
    const long inB = (long)b * Cin * Hin * Win;

    for (int ci0 = 0; ci0 < Cin; ci0 += CK) {
        __syncthreads();
        // ---- input patch (deinterleaved, zero-filled OOB) ----
        for (int idx = tid; idx < CK * IR * TC; idx += 256) {
            int j  = idx % TC;
            int r  = (idx / TC) % IR;
            int ci = idx / (TC * IR);
            int iy = iy_org + r, ix = ix_org + j;
            int cig = ci0 + ci;
            float v = 0.f;
            if (cig < Cin && iy >= 0 && iy < Hin && ix >= 0 && ix < Win)
                v = in[inB + ((long)cig * Hin + iy) * Win + ix];
            if (j & 1) od_s[ci][r][j >> 1] = v;
            else       ev_s[ci][r][j >> 1] = v;
        }
        // ---- weights ----
        for (int idx = tid; idx < CK * 16 * 32; idx += 256) {
            int cl = idx & 31;
            int t  = (idx >> 5) & 15;
            int ci = idx >> 9;
            int cig = ci0 + ci;
            float v = 0.f;
            if (cig < Cin)
                v = w[((long)(co0 + cl) * Cin + cig) * 16 + t];
            w_s[ci][t][cl] = v;
        }
        __syncthreads();

        #pragma unroll 1
        for (int ci = 0; ci < CK; ci++) {
            #pragma unroll
            for (int q = 0; q < 2; q++) {       // row parity; ky in {q, q+2}
                float4 w0[4], w2[4];
                #pragma unroll
                for (int kx = 0; kx < 4; kx++) {
                    w0[kx] = *reinterpret_cast<const float4*>(&w_s[ci][ q      * 4 + kx][cg4]);
                    w2[kx] = *reinterpret_cast<const float4*>(&w_s[ci][(q + 2) * 4 + kx][cg4]);
                }
                #pragma unroll
                for (int j = 0; j <= RPT; j++) {
                    const int r = rbase + 2 * j + q;
                    float ae0 = ev_s[ci][r][colx];
                    float ao0 = od_s[ci][r][colx];
                    float ae1 = ev_s[ci][r][colx + 1];
                    float ao1 = od_s[ci][r][colx + 1];
                    if (j < RPT) {              // ky = q, output row j
                        fma4(acc[j], ae0, w0[0]); fma4(acc[j], ao0, w0[1]);
                        fma4(acc[j], ae1, w0[2]); fma4(acc[j], ao1, w0[3]);
                    }
                    if (j > 0) {                // ky = q+2, output row j-1
                        fma4(acc[j-1], ae0, w2[0]); fma4(acc[j-1], ao0, w2[1]);
                        fma4(acc[j-1], ae1, w2[2]); fma4(acc[j-1], ao1, w2[3]);
                    }
                }
            }
        }
    }

    const long outB = (long)b * Cout * Hout * Wout;
    const int  ox = ox0 + colx;
    #pragma unroll
    for (int c = 0; c < 4; c++) {
        const int co = co0 + cg4 + c;
        const float bv = bias[co];
        #pragma unroll
        for (int i = 0; i < RPT; i++) {
            const int oy = oy0 + rg * RPT + i;
            out[outB + ((long)co * Hout + oy) * Wout + ox] = fmaxf(acc[i][c] + bv, 0.f);
        }
    }
}

// ---------------------------------------------------------------------------
// ConvTranspose: k=4, s=2, p=1, ReLU. w layout (Cin, Cout, 4, 4).
// oy = 2*iy - 1 + ky. Lane owns one INPUT column (2 output cols), 2 input
// rows (4 output rows). 4 parity sub-convolutions; activation loads stride-1.
// ---------------------------------------------------------------------------
template<int TWI, int CK>
__global__ __launch_bounds__(256)
void convt(const float* __restrict__ in, const float* __restrict__ w,
           const float* __restrict__ bias, float* __restrict__ out,
           int Cin, int Hin, int Win, int Cout)
{
    constexpr int PRT  = 2;                 // input rows per thread
    constexpr int RGI  = 32 / TWI;
    constexpr int BIR  = PRT * RGI;         // block input rows
    constexpr int PIR  = BIR + 2;           // patch rows (halo)
    constexpr int PIC  = TWI + 2;           // patch cols
    constexpr int PICP = (TWI == 16) ? 24 : 35; // pitch (conflict-free)

    __shared__ float in_s[CK][PIR][PICP];
    __shared__ __align__(16) float w_s[CK][16][32];

    const int Hout = Hin * 2, Wout = Win * 2;
    const int colb = Win / TWI;
    const int tx = blockIdx.x % colb;
    const int ry = blockIdx.x / colb;
    const int Rbase = ry * BIR;
    const int c0 = tx * TWI;
    const int co0 = blockIdx.y * 32;
    const int b   = blockIdx.z;

    const int tid  = threadIdx.x;
    const int cg   = tid >> 5;
    const int lane = tid & 31;
    const int cI   = lane % TWI;
    const int rgI  = lane / TWI;
    const int cg4  = cg * 4;
    const int prbase = rgI * PRT;
    const int pcol = cI + 1;

    float acc[2][2][2][4];                  // [iR][py][px][c]
    #pragma unroll
    for (int i = 0; i < 2; i++)
        #pragma unroll
        for (int p = 0; p < 2; p++)
            #pragma unroll
            for (int q = 0; q < 2; q++)
                #pragma unroll
                for (int c = 0; c < 4; c++) acc[i][p][q][c] = 0.f;

    const long inB = (long)b * Cin * Hin * Win;

    for (int ci0 = 0; ci0 < Cin; ci0 += CK) {
        __syncthreads();
        for (int idx = tid; idx < CK * PIR * PIC; idx += 256) {
            int j  = idx % PIC;
            int pr = (idx / PIC) % PIR;
            int ci = idx / (PIC * PIR);
            int iy = Rbase - 1 + pr, ix = c0 - 1 + j;
            int cig = ci0 + ci;
            float v = 0.f;
            if (cig < Cin && iy >= 0 && iy < Hin && ix >= 0 && ix < Win)
                v = in[inB + ((long)cig * Hin + iy) * Win + ix];
            in_s[ci][pr][j] = v;
        }
        for (int idx = tid; idx < CK * 16 * 32; idx += 256) {
            int cl = idx & 31;
            int t  = (idx >> 5) & 15;
            int ci = idx >> 9;
            int cig = ci0 + ci;
            float v = 0.f;
            if (cig < Cin)
                v = w[((long)cig * Cout + (co0 + cl)) * 16 + t];
            w_s[ci][t][cl] = v;
        }
        __syncthreads();

        #pragma unroll 1
        for (int ci = 0; ci < CK; ci++) {
            #pragma unroll
            for (int px = 0; px < 2; px++) {
                float4 wk[4][2];            // [ky][kxi], kx = (px^1) + 2*kxi
                #pragma unroll
                for (int ky = 0; ky < 4; ky++)
                    #pragma unroll
                    for (int kxi = 0; kxi < 2; kxi++)
                        wk[ky][kxi] = *reinterpret_cast<const float4*>(
                            &w_s[ci][ky * 4 + (px ^ 1) + 2 * kxi][cg4]);
                const int ca = pcol + px;       // kxi=0
                const int cb = pcol + px - 1;   // kxi=1
                #pragma unroll
                for (int jr = 0; jr < 4; jr++) {
                    const int pr = prbase + jr;
                    float a0 = in_s[ci][pr][ca];
                    float a1 = in_s[ci][pr][cb];
                    // iy == R   (jr-1): py=0 ky=1; py=1 ky=2
                    if (jr >= 1 && jr <= 2) {
                        fma4(acc[jr-1][0][px], a0, wk[1][0]); fma4(acc[jr-1][0][px], a1, wk[1][1]);
                        fma4(acc[jr-1][1][px], a0, wk[2][0]); fma4(acc[jr-1][1][px], a1, wk[2][1]);
                    }
                    // iy == R-1 (jr):   py=0 ky=3
                    if (jr < 2) {
                        fma4(acc[jr][0][px], a0, wk[3][0]); fma4(acc[jr][0][px], a1, wk[3][1]);
                    }
                    // iy == R+1 (jr-2): py=1 ky=0
                    if (jr >= 2) {
                        fma4(acc[jr-2][1][px], a0, wk[0][0]); fma4(acc[jr-2][1][px], a1, wk[0][1]);
                    }
                }
            }
        }
    }

    const long outB = (long)b * Cout * Hout * Wout;
    const int  oxp = 2 * (c0 + cI);
    #pragma unroll
    for (int c = 0; c < 4; c++) {
        const int co = co0 + cg4 + c;
        const float bv = bias[co];
        #pragma unroll
        for (int iR = 0; iR < 2; iR++) {
            #pragma unroll
            for (int py = 0; py < 2; py++) {
                const int oy = 2 * (Rbase + prbase + iR) + py;
                float2 v;
                v.x = fmaxf(acc[iR][py][0][c] + bv, 0.f);
                v.y = fmaxf(acc[iR][py][1][c] + bv, 0.f);
                *reinterpret_cast<float2*>(&out[outB + ((long)co * Hout + oy) * Wout + oxp]) = v;
            }
        }
    }
}

// ---------------------------------------------------------------------------
// Final ConvT layer: Cin=32, Cout=3, tanh. smem input tile + smem weights.
// ---------------------------------------------------------------------------
__global__ __launch_bounds__(256)
void convt_final_kernel(const float* __restrict__ in, const float* __restrict__ w,
                        const float* __restrict__ bias, float* __restrict__ out)
{
    const int Cin = 32, Hin = 128, Win = 128, Hout = 256, Wout = 256;
    __shared__ float in_s[32][10][11];
    __shared__ float w_s[32][3][16];

    const int tid = threadIdx.x;
    const int b = blockIdx.z;
    const int tx = blockIdx.x & 15;
    const int ty = blockIdx.x >> 4;
    const int oy0 = ty * 16, ox0 = tx * 16;
    const int iyb = oy0 / 2 - 1, ixb = ox0 / 2 - 1;

    for (int i = tid; i < 32 * 3 * 16; i += 256)
        ((float*)w_s)[i] = w[i];
    const float* inb = in + (long)b * Cin * Hin * Win;
    for (int idx = tid; idx < 3200; idx += 256) {
        int c  = idx % 10;
        int r  = (idx / 10) % 10;
        int ci = idx / 100;
        int iy = iyb + r, ix = ixb + c;
        float v = 0.f;
        if (iy >= 0 && iy < Hin && ix >= 0 && ix < Win)
            v = inb[((long)ci * Hin + iy) * Win + ix];
        in_s[ci][r][c] = v;
    }
    __syncthreads();

    const int ox = ox0 + (tid & 15);
    const int oy = oy0 + (tid >> 4);
    const int ky0 = (oy + 1) & 1;
    const int kx0 = (ox + 1) & 1;

    float a0 = bias[0], a1 = bias[1], a2 = bias[2];
    #pragma unroll
    for (int kyi = 0; kyi < 2; kyi++) {
        #pragma unroll
        for (int kxi = 0; kxi < 2; kxi++) {
            const int ky = ky0 + 2 * kyi, kx = kx0 + 2 * kxi;
            const int pr = (oy + 1 - ky) / 2 - iyb;
            const int pc = (ox + 1 - kx) / 2 - ixb;
            const int t = ky * 4 + kx;
            #pragma unroll 8
            for (int ci = 0; ci < 32; ci++) {
                float v = in_s[ci][pr][pc];
                a0 += v * w_s[ci][0][t];
                a1 += v * w_s[ci][1][t];
                a2 += v * w_s[ci][2][t];
            }
        }
    }
    const long o = (long)b * 3 * Hout * Wout + (long)oy * Wout + ox;
    out[o]                    = tanhf(a0);
    out[o + (long)Hout*Wout]  = tanhf(a1);
    out[o + 2L*Hout*Wout]     = tanhf(a2);
}

// ---------------------------------------------------------------------------
// Quantizer
// ---------------------------------------------------------------------------
__global__ void e2_kernel(const float* __restrict__ embed, float* __restrict__ e2)
{
    int k = blockIdx.x * blockDim.x + threadIdx.x;
    if (k >= 1024) return;
    const float* e = embed + (long)k * 512;
    float s = 0.f;
    #pragma unroll 4
    for (int d = 0; d < 512; d++) { float v = e[d]; s += v * v; }
    e2[k] = s;
}

__global__ __launch_bounds__(128)
void argmin_kernel(const float* __restrict__ z, const float* __restrict__ embed,
                   const float* __restrict__ e2, int* __restrict__ idx_out)
{
    __shared__ float z_s[512][8];
    __shared__ float rv[8][128];
    __shared__ int   ri[8][128];
    const int tid = threadIdx.x;
    const int n0 = blockIdx.x * 8;
    const int b = n0 >> 8;
    const int pix0 = n0 & 255;
    const float* zb = z + (long)b * 512 * 256 + pix0;

    for (int i = tid; i < 512 * 8; i += 128) {
        int d = i >> 3, nl = i & 7;
        z_s[d][nl] = zb[(long)d * 256 + nl];
    }
    __syncthreads();

    float bv[8]; int bi[8];
    #pragma unroll
    for (int nl = 0; nl < 8; nl++) { bv[nl] = 3.4e38f; bi[nl] = 0; }

    for (int k = tid; k < 1024; k += 128) {
        const float* e = embed + (long)k * 512;
        float dot[8];
        #pragma unroll
        for (int nl = 0; nl < 8; nl++) dot[nl] = 0.f;
        #pragma unroll 4
        for (int d = 0; d < 512; d++) {
            float evv = e[d];
            #pragma unroll
            for (int nl = 0; nl < 8; nl++) dot[nl] += evv * z_s[d][nl];
        }
        float c = e2[k];
        #pragma unroll
        for (int nl = 0; nl < 8; nl++) {
            float dist = c - 2.f * dot[nl];
            if (dist < bv[nl]) { bv[nl] = dist; bi[nl] = k; }
        }
    }
    #pragma unroll
    for (int nl = 0; nl < 8; nl++) { rv[nl][tid] = bv[nl]; ri[nl][tid] = bi[nl]; }
    __syncthreads();
    if (tid < 8) {
        float best = rv[tid][0]; int besti = ri[tid][0];
        for (int j = 1; j < 128; j++) {
            float v = rv[tid][j]; int ii = ri[tid][j];
            if (v < best || (v == best && ii < besti)) { best = v; besti = ii; }
        }
        idx_out[n0 + tid] = besti;
    }
}

__global__ void gather_kernel(const int* __restrict__ idx, const float* __restrict__ embed,
                              float* __restrict__ zq)
{
    const int n = blockIdx.x;
    const int b = n >> 8, pix = n & 255;
    const float* e = embed + (long)idx[n] * 512;
    float* o = zq + (long)b * 512 * 256 + pix;
    for (int d = threadIdx.x; d < 512; d += 256)
        o[(long)d * 256] = e[d];
}

// ---------------------------------------------------------------------------
// Launch
// ---------------------------------------------------------------------------
extern "C" void kernel_launch(void* const* d_in, const int* in_sizes, int n_in,
                              void* d_out, int out_size)
{
    const float* x     = (const float*)d_in[0];
    const float* ew1   = (const float*)d_in[1];
    const float* eb1   = (const float*)d_in[2];
    const float* ew2   = (const float*)d_in[3];
    const float* eb2   = (const float*)d_in[4];
    const float* ew3   = (const float*)d_in[5];
    const float* eb3   = (const float*)d_in[6];
    const float* ew4   = (const float*)d_in[7];
    const float* eb4   = (const float*)d_in[8];
    const float* dw1   = (const float*)d_in[9];
    const float* db1   = (const float*)d_in[10];
    const float* dw2   = (const float*)d_in[11];
    const float* db2   = (const float*)d_in[12];
    const float* dw3   = (const float*)d_in[13];
    const float* db3   = (const float*)d_in[14];
    const float* dw4   = (const float*)d_in[15];
    const float* db4   = (const float*)d_in[16];
    const float* embed = (const float*)d_in[17];
    float* out = (float*)d_out;

    float *A, *B, *e2p; int* idxp;
    cudaGetSymbolAddress((void**)&A,    g_bufA);
    cudaGetSymbolAddress((void**)&B,    g_bufB);
    cudaGetSymbolAddress((void**)&e2p,  g_e2);
    cudaGetSymbolAddress((void**)&idxp, g_idx);

    const int NB = 32;

    // ---- encoder ----
    // e1: (3,256,256)->(64,128,128): tiles 4x32, couts 2
    conv_enc<32,4,4><<<dim3(128, 2, NB), 256>>>(x,  ew1, eb1, A, 3,   256, 256, 64);
    // e2: (64,128,128)->(128,64,64): tiles 2x16, couts 4
    conv_enc<32,4,8><<<dim3(32, 4, NB), 256>>>(A,  ew2, eb2, B, 64,  128, 128, 128);
    // e3: (128,64,64)->(256,32,32): tiles 1x8, couts 8
    conv_enc<32,4,8><<<dim3(8,  8, NB), 256>>>(B,  ew3, eb3, A, 128, 64,  64,  256);
    // e4: (256,32,32)->(512,16,16): tiles 1x2, couts 16
    conv_enc<16,8,8><<<dim3(2, 16, NB), 256>>>(A,  ew4, eb4, B, 256, 32,  32,  512);

    // ---- quantizer ----
    e2_kernel<<<4, 256>>>(embed, e2p);
    argmin_kernel<<<1024, 128>>>(B, embed, e2p, idxp);
    gather_kernel<<<8192, 256>>>(idxp, embed, A);          // zq in A

    // ---- decoder ----
    // d1: (512,16,16)->(128,32,32): rowb 4, colb 1, couts 4
    convt<16,8><<<dim3(4,  4, NB), 256>>>(A, dw1, db1, B, 512, 16,  16,  128);
    // d2: (128,32,32)->(64,64,64): rowb 16, colb 1, couts 2
    convt<32,8><<<dim3(16, 2, NB), 256>>>(B, dw2, db2, A, 128, 32,  32,  64);
    // d3: (64,64,64)->(32,128,128): rowb 32, colb 2, couts 1
    convt<32,8><<<dim3(64, 1, NB), 256>>>(A, dw3, db3, B, 64,  64,  64,  32);
    // d4: (32,128,128)->(3,256,256) + tanh
    convt_final_kernel<<<dim3(256, 1, NB), 256>>>(B, dw4, db4, out);
}

// round 4
// speedup vs baseline: 1.0565x; 1.0565x over previous
#include <cuda_runtime.h>
#include <math.h>

// ---------------------------------------------------------------------------
// Scratch (device globals; no allocation anywhere)
// ---------------------------------------------------------------------------
static __device__ float g_bufA[33554432];   // 134 MB
static __device__ float g_bufB[16777216];   //  67 MB
static __device__ int   g_idx[8192];
static __device__ float g_e2[1024];

__device__ __forceinline__ void fma4(float* acc, float a, float4 w) {
    acc[0] += a * w.x; acc[1] += a * w.y; acc[2] += a * w.z; acc[3] += a * w.w;
}

// ---------------------------------------------------------------------------
// Encoder conv: k=4, s=2, p=1, ReLU.  in NCHW, w OIHW.
// Block 256 thr = 8 warps; each warp owns 8 couts (block: 64 couts).
// Lane owns one output column, RPT output rows. Input patch de-interleaved
// into even/odd column planes (stride-1 conflict-free LDS). Weight LDS.128
// are warp-broadcast. kx innermost with only 4 weight vectors live.
// ---------------------------------------------------------------------------
template<int TW, int TH, int CK>
__global__ __launch_bounds__(256, 3)
void conv_enc(const float* __restrict__ in, const float* __restrict__ w,
              const float* __restrict__ bias, float* __restrict__ out,
              int Cin, int Hin, int Win, int Cout)
{
    constexpr int RG  = 32 / TW;        // row groups per warp
    constexpr int RPT = TH / RG;        // output rows per thread (=4)
    constexpr int IR  = 2 * TH + 2;     // input patch rows
    constexpr int HCP = (TW == 16) ? 18 : 33;  // parity-plane pitch
    constexpr int TC  = 2 * TW + 2;     // input patch cols

    __shared__ float ev_s[CK][IR][HCP];
    __shared__ float od_s[CK][IR][HCP];
    __shared__ __align__(16) float w_s[CK][16][64];

    const int Hout = Hin >> 1, Wout = Win >> 1;
    const int tiles_x = Wout / TW;
    const int tx = blockIdx.x % tiles_x;
    const int ty = blockIdx.x / tiles_x;
    const int oy0 = ty * TH, ox0 = tx * TW;
    const int co0 = blockIdx.y * 64;
    const int b   = blockIdx.z;

    const int tid  = threadIdx.x;
    const int cg   = tid >> 5;               // warp -> 8-cout group
    const int lane = tid & 31;
    const int colx = lane % TW;
    const int rg   = lane / TW;
    const int cg8  = cg * 8;
    const int rbase = 2 * rg * RPT;

    float acc[RPT][8];
    #pragma unroll
    for (int i = 0; i < RPT; i++)
        #pragma unroll
        for (int c = 0; c < 8; c++) acc[i][c] = 0.f;

    const int  iy_org = 2 * oy0 - 1;
    const int  ix_org = 2 * ox0 - 1;
    const long inB = (long)b * Cin * Hin * Win;

    for (int ci0 = 0; ci0 < Cin; ci0 += CK) {
        __syncthreads();
        // ---- input patch (deinterleaved, zero-filled OOB) ----
        for (int idx = tid; idx < CK * IR * TC; idx += 256) {
            int j  = idx % TC;
            int r  = (idx / TC) % IR;
            int ci = idx / (TC * IR);
            int iy = iy_org + r, ix = ix_org + j;
            int cig = ci0 + ci;
            float v = 0.f;
            if (cig < Cin && iy >= 0 && iy < Hin && ix >= 0 && ix < Win)
                v = in[inB + ((long)cig * Hin + iy) * Win + ix];
            if (j & 1) od_s[ci][r][j >> 1] = v;
            else       ev_s[ci][r][j >> 1] = v;
        }
        // ---- weights ----
        for (int idx = tid; idx < CK * 16 * 64; idx += 256) {
            int cl = idx & 63;
            int t  = (idx >> 6) & 15;
            int ci = idx >> 10;
            int cig = ci0 + ci;
            float v = 0.f;
            if (cig < Cin)
                v = w[((long)(co0 + cl) * Cin + cig) * 16 + t];
            w_s[ci][t][cl] = v;
        }
        __syncthreads();

        #pragma unroll 1
        for (int ci = 0; ci < CK; ci++) {
            #pragma unroll
            for (int q = 0; q < 2; q++) {         // row parity; ky in {q,q+2}
                #pragma unroll
                for (int kx = 0; kx < 4; kx++) {
                    const float* pl = (kx & 1) ? &od_s[ci][0][0] : &ev_s[ci][0][0];
                    const int off = colx + (kx >> 1);
                    float4 w0a = *reinterpret_cast<const float4*>(&w_s[ci][ q      * 4 + kx][cg8]);
                    float4 w0b = *reinterpret_cast<const float4*>(&w_s[ci][ q      * 4 + kx][cg8 + 4]);
                    float4 w2a = *reinterpret_cast<const float4*>(&w_s[ci][(q + 2) * 4 + kx][cg8]);
                    float4 w2b = *reinterpret_cast<const float4*>(&w_s[ci][(q + 2) * 4 + kx][cg8 + 4]);
                    #pragma unroll
                    for (int j = 0; j <= RPT; j++) {
                        float a = pl[(rbase + 2 * j + q) * HCP + off];
                        if (j < RPT) {            // ky = q -> output row j
                            fma4(acc[j],     a, w0a);
                            fma4(acc[j] + 4, a, w0b);
                        }
                        if (j > 0) {              // ky = q+2 -> output row j-1
                            fma4(acc[j-1],     a, w2a);
                            fma4(acc[j-1] + 4, a, w2b);
                        }
                    }
                }
            }
        }
    }

    const long outB = (long)b * Cout * Hout * Wout;
    const int  ox = ox0 + colx;
    #pragma unroll
    for (int c = 0; c < 8; c++) {
        const int co = co0 + cg8 + c;
        const float bv = bias[co];
        #pragma unroll
        for (int i = 0; i < RPT; i++) {
            const int oy = oy0 + rg * RPT + i;
            out[outB + ((long)co * Hout + oy) * Wout + ox] = fmaxf(acc[i][c] + bv, 0.f);
        }
    }
}

// ---------------------------------------------------------------------------
// ConvTranspose: k=4, s=2, p=1, ReLU. w layout (Cin, Cout, 4, 4).
// (unchanged from passing R3 version)
// ---------------------------------------------------------------------------
template<int TWI, int CK>
__global__ __launch_bounds__(256)
void convt(const float* __restrict__ in, const float* __restrict__ w,
           const float* __restrict__ bias, float* __restrict__ out,
           int Cin, int Hin, int Win, int Cout)
{
    constexpr int PRT  = 2;
    constexpr int RGI  = 32 / TWI;
    constexpr int BIR  = PRT * RGI;
    constexpr int PIR  = BIR + 2;
    constexpr int PIC  = TWI + 2;
    constexpr int PICP = (TWI == 16) ? 24 : 35;

    __shared__ float in_s[CK][PIR][PICP];
    __shared__ __align__(16) float w_s[CK][16][32];

    const int Hout = Hin * 2, Wout = Win * 2;
    const int colb = Win / TWI;
    const int tx = blockIdx.x % colb;
    const int ry = blockIdx.x / colb;
    const int Rbase = ry * BIR;
    const int c0 = tx * TWI;
    const int co0 = blockIdx.y * 32;
    const int b   = blockIdx.z;

    const int tid  = threadIdx.x;
    const int cg   = tid >> 5;
    const int lane = tid & 31;
    const int cI   = lane % TWI;
    const int rgI  = lane / TWI;
    const int cg4  = cg * 4;
    const int prbase = rgI * PRT;
    const int pcol = cI + 1;

    float acc[2][2][2][4];
    #pragma unroll
    for (int i = 0; i < 2; i++)
        #pragma unroll
        for (int p = 0; p < 2; p++)
            #pragma unroll
            for (int q = 0; q < 2; q++)
                #pragma unroll
                for (int c = 0; c < 4; c++) acc[i][p][q][c] = 0.f;

    const long inB = (long)b * Cin * Hin * Win;

    for (int ci0 = 0; ci0 < Cin; ci0 += CK) {
        __syncthreads();
        for (int idx = tid; idx < CK * PIR * PIC; idx += 256) {
            int j  = idx % PIC;
            int pr = (idx / PIC) % PIR;
            int ci = idx / (PIC * PIR);
            int iy = Rbase - 1 + pr, ix = c0 - 1 + j;
            int cig = ci0 + ci;
            float v = 0.f;
            if (cig < Cin && iy >= 0 && iy < Hin && ix >= 0 && ix < Win)
                v = in[inB + ((long)cig * Hin + iy) * Win + ix];
            in_s[ci][pr][j] = v;
        }
        for (int idx = tid; idx < CK * 16 * 32; idx += 256) {
            int cl = idx & 31;
            int t  = (idx >> 5) & 15;
            int ci = idx >> 9;
            int cig = ci0 + ci;
            float v = 0.f;
            if (cig < Cin)
                v = w[((long)cig * Cout + (co0 + cl)) * 16 + t];
            w_s[ci][t][cl] = v;
        }
        __syncthreads();

        #pragma unroll 1
        for (int ci = 0; ci < CK; ci++) {
            #pragma unroll
            for (int px = 0; px < 2; px++) {
                float4 wk[4][2];
                #pragma unroll
                for (int ky = 0; ky < 4; ky++)
                    #pragma unroll
                    for (int kxi = 0; kxi < 2; kxi++)
                        wk[ky][kxi] = *reinterpret_cast<const float4*>(
                            &w_s[ci][ky * 4 + (px ^ 1) + 2 * kxi][cg4]);
                const int ca = pcol + px;
                const int cb = pcol + px - 1;
                #pragma unroll
                for (int jr = 0; jr < 4; jr++) {
                    const int pr = prbase + jr;
                    float a0 = in_s[ci][pr][ca];
                    float a1 = in_s[ci][pr][cb];
                    if (jr >= 1 && jr <= 2) {
                        fma4(acc[jr-1][0][px], a0, wk[1][0]); fma4(acc[jr-1][0][px], a1, wk[1][1]);
                        fma4(acc[jr-1][1][px], a0, wk[2][0]); fma4(acc[jr-1][1][px], a1, wk[2][1]);
                    }
                    if (jr < 2) {
                        fma4(acc[jr][0][px], a0, wk[3][0]); fma4(acc[jr][0][px], a1, wk[3][1]);
                    }
                    if (jr >= 2) {
                        fma4(acc[jr-2][1][px], a0, wk[0][0]); fma4(acc[jr-2][1][px], a1, wk[0][1]);
                    }
                }
            }
        }
    }

    const long outB = (long)b * Cout * Hout * Wout;
    const int  oxp = 2 * (c0 + cI);
    #pragma unroll
    for (int c = 0; c < 4; c++) {
        const int co = co0 + cg4 + c;
        const float bv = bias[co];
        #pragma unroll
        for (int iR = 0; iR < 2; iR++) {
            #pragma unroll
            for (int py = 0; py < 2; py++) {
                const int oy = 2 * (Rbase + prbase + iR) + py;
                float2 v;
                v.x = fmaxf(acc[iR][py][0][c] + bv, 0.f);
                v.y = fmaxf(acc[iR][py][1][c] + bv, 0.f);
                *reinterpret_cast<float2*>(&out[outB + ((long)co * Hout + oy) * Wout + oxp]) = v;
            }
        }
    }
}

// ---------------------------------------------------------------------------
// Final ConvT layer: Cin=32, Cout=3, tanh.
// ---------------------------------------------------------------------------
__global__ __launch_bounds__(256)
void convt_final_kernel(const float* __restrict__ in, const float* __restrict__ w,
                        const float* __restrict__ bias, float* __restrict__ out)
{
    const int Cin = 32, Hin = 128, Win = 128, Hout = 256, Wout = 256;
    __shared__ float in_s[32][10][11];
    __shared__ float w_s[32][3][16];

    const int tid = threadIdx.x;
    const int b = blockIdx.z;
    const int tx = blockIdx.x & 15;
    const int ty = blockIdx.x >> 4;
    const int oy0 = ty * 16, ox0 = tx * 16;
    const int iyb = oy0 / 2 - 1, ixb = ox0 / 2 - 1;

    for (int i = tid; i < 32 * 3 * 16; i += 256)
        ((float*)w_s)[i] = w[i];
    const float* inb = in + (long)b * Cin * Hin * Win;
    for (int idx = tid; idx < 3200; idx += 256) {
        int c  = idx % 10;
        int r  = (idx / 10) % 10;
        int ci = idx / 100;
        int iy = iyb + r, ix = ixb + c;
        float v = 0.f;
        if (iy >= 0 && iy < Hin && ix >= 0 && ix < Win)
            v = inb[((long)ci * Hin + iy) * Win + ix];
        in_s[ci][r][c] = v;
    }
    __syncthreads();

    const int ox = ox0 + (tid & 15);
    const int oy = oy0 + (tid >> 4);
    const int ky0 = (oy + 1) & 1;
    const int kx0 = (ox + 1) & 1;

    float a0 = bias[0], a1 = bias[1], a2 = bias[2];
    #pragma unroll
    for (int kyi = 0; kyi < 2; kyi++) {
        #pragma unroll
        for (int kxi = 0; kxi < 2; kxi++) {
            const int ky = ky0 + 2 * kyi, kx = kx0 + 2 * kxi;
            const int pr = (oy + 1 - ky) / 2 - iyb;
            const int pc = (ox + 1 - kx) / 2 - ixb;
            const int t = ky * 4 + kx;
            #pragma unroll 8
            for (int ci = 0; ci < 32; ci++) {
                float v = in_s[ci][pr][pc];
                a0 += v * w_s[ci][0][t];
                a1 += v * w_s[ci][1][t];
                a2 += v * w_s[ci][2][t];
            }
        }
    }
    const long o = (long)b * 3 * Hout * Wout + (long)oy * Wout + ox;
    out[o]                    = tanhf(a0);
    out[o + (long)Hout*Wout]  = tanhf(a1);
    out[o + 2L*Hout*Wout]     = tanhf(a2);
}

// ---------------------------------------------------------------------------
// Quantizer
// ---------------------------------------------------------------------------
__global__ void e2_kernel(const float* __restrict__ embed, float* __restrict__ e2)
{
    int k = blockIdx.x * blockDim.x + threadIdx.x;
    if (k >= 1024) return;
    const float* e = embed + (long)k * 512;
    float s = 0.f;
    #pragma unroll 4
    for (int d = 0; d < 512; d++) { float v = e[d]; s += v * v; }
    e2[k] = s;
}

__global__ __launch_bounds__(128)
void argmin_kernel(const float* __restrict__ z, const float* __restrict__ embed,
                   const float* __restrict__ e2, int* __restrict__ idx_out)
{
    __shared__ float z_s[512][8];
    __shared__ float rv[8][128];
    __shared__ int   ri[8][128];
    const int tid = threadIdx.x;
    const int n0 = blockIdx.x * 8;
    const int b = n0 >> 8;
    const int pix0 = n0 & 255;
    const float* zb = z + (long)b * 512 * 256 + pix0;

    for (int i = tid; i < 512 * 8; i += 128) {
        int d = i >> 3, nl = i & 7;
        z_s[d][nl] = zb[(long)d * 256 + nl];
    }
    __syncthreads();

    float bv[8]; int bi[8];
    #pragma unroll
    for (int nl = 0; nl < 8; nl++) { bv[nl] = 3.4e38f; bi[nl] = 0; }

    for (int k = tid; k < 1024; k += 128) {
        const float* e = embed + (long)k * 512;
        float dot[8];
        #pragma unroll
        for (int nl = 0; nl < 8; nl++) dot[nl] = 0.f;
        #pragma unroll 4
        for (int d = 0; d < 512; d++) {
            float evv = e[d];
            #pragma unroll
            for (int nl = 0; nl < 8; nl++) dot[nl] += evv * z_s[d][nl];
        }
        float c = e2[k];
        #pragma unroll
        for (int nl = 0; nl < 8; nl++) {
            float dist = c - 2.f * dot[nl];
            if (dist < bv[nl]) { bv[nl] = dist; bi[nl] = k; }
        }
    }
    #pragma unroll
    for (int nl = 0; nl < 8; nl++) { rv[nl][tid] = bv[nl]; ri[nl][tid] = bi[nl]; }
    __syncthreads();
    if (tid < 8) {
        float best = rv[tid][0]; int besti = ri[tid][0];
        for (int j = 1; j < 128; j++) {
            float v = rv[tid][j]; int ii = ri[tid][j];
            if (v < best || (v == best && ii < besti)) { best = v; besti = ii; }
        }
        idx_out[n0 + tid] = besti;
    }
}

__global__ void gather_kernel(const int* __restrict__ idx, const float* __restrict__ embed,
                              float* __restrict__ zq)
{
    const int n = blockIdx.x;
    const int b = n >> 8, pix = n & 255;
    const float* e = embed + (long)idx[n] * 512;
    float* o = zq + (long)b * 512 * 256 + pix;
    for (int d = threadIdx.x; d < 512; d += 256)
        o[(long)d * 256] = e[d];
}

// ---------------------------------------------------------------------------
// Launch
// ---------------------------------------------------------------------------
extern "C" void kernel_launch(void* const* d_in, const int* in_sizes, int n_in,
                              void* d_out, int out_size)
{
    const float* x     = (const float*)d_in[0];
    const float* ew1   = (const float*)d_in[1];
    const float* eb1   = (const float*)d_in[2];
    const float* ew2   = (const float*)d_in[3];
    const float* eb2   = (const float*)d_in[4];
    const float* ew3   = (const float*)d_in[5];
    const float* eb3   = (const float*)d_in[6];
    const float* ew4   = (const float*)d_in[7];
    const float* eb4   = (const float*)d_in[8];
    const float* dw1   = (const float*)d_in[9];
    const float* db1   = (const float*)d_in[10];
    const float* dw2   = (const float*)d_in[11];
    const float* db2   = (const float*)d_in[12];
    const float* dw3   = (const float*)d_in[13];
    const float* db3   = (const float*)d_in[14];
    const float* dw4   = (const float*)d_in[15];
    const float* db4   = (const float*)d_in[16];
    const float* embed = (const float*)d_in[17];
    float* out = (float*)d_out;

    float *A, *B, *e2p; int* idxp;
    cudaGetSymbolAddress((void**)&A,    g_bufA);
    cudaGetSymbolAddress((void**)&B,    g_bufB);
    cudaGetSymbolAddress((void**)&e2p,  g_e2);
    cudaGetSymbolAddress((void**)&idxp, g_idx);

    const int NB = 32;

    // ---- encoder (64 couts per block) ----
    // e1: (3,256,256)->(64,128,128): tiles (128/32)*(128/4)=128, couts 64/64=1
    conv_enc<32,4,4><<<dim3(128, 1, NB), 256>>>(x,  ew1, eb1, A, 3,   256, 256, 64);
    // e2: (64,128,128)->(128,64,64): tiles (64/32)*(64/4)=32, couts 2
    conv_enc<32,4,4><<<dim3(32, 2, NB), 256>>>(A,  ew2, eb2, B, 64,  128, 128, 128);
    // e3: (128,64,64)->(256,32,32): tiles (32/32)*(32/4)=8, couts 4
    conv_enc<32,4,4><<<dim3(8,  4, NB), 256>>>(B,  ew3, eb3, A, 128, 64,  64,  256);
    // e4: (256,32,32)->(512,16,16): tiles (16/16)*(16/8)=2, couts 8
    conv_enc<16,8,4><<<dim3(2,  8, NB), 256>>>(A,  ew4, eb4, B, 256, 32,  32,  512);

    // ---- quantizer ----
    e2_kernel<<<4, 256>>>(embed, e2p);
    argmin_kernel<<<1024, 128>>>(B, embed, e2p, idxp);
    gather_kernel<<<8192, 256>>>(idxp, embed, A);          // zq in A

    // ---- decoder ----
    convt<16,8><<<dim3(4,  4, NB), 256>>>(A, dw1, db1, B, 512, 16,  16,  128);
    convt<32,8><<<dim3(16, 2, NB), 256>>>(B, dw2, db2, A, 128, 32,  32,  64);
    convt<32,8><<<dim3(64, 1, NB), 256>>>(A, dw3, db3, B, 64,  64,  64,  32);
    convt_final_kernel<<<dim3(256, 1, NB), 256>>>(B, dw4, db4, out);
}

// round 5
// speedup vs baseline: 1.1087x; 1.0495x over previous
#include <cuda_runtime.h>
#include <math.h>

// ---------------------------------------------------------------------------
// Scratch (device globals; no allocation anywhere)
// ---------------------------------------------------------------------------
static __device__ float g_bufA[33554432];   // 134 MB
static __device__ float g_bufB[16777216];   //  67 MB
static __device__ int   g_idx[8192];
static __device__ float g_e2[1024];

typedef unsigned long long ull;

// packed f32x2 FMA: d = a*b + d  (two independent fp32 FMAs, exact)
__device__ __forceinline__ void ffma2(ull& d, ull a, ull b) {
    asm("fma.rn.f32x2 %0, %1, %2, %0;" : "+l"(d) : "l"(a), "l"(b));
}
// broadcast one float into both halves of a 64-bit packed pair
__device__ __forceinline__ ull pack2(float a) {
    ull r; unsigned int ai = __float_as_uint(a);
    asm("mov.b64 %0, {%1, %1};" : "=l"(r) : "r"(ai));
    return r;
}
__device__ __forceinline__ float2 upk(ull v) {
    union { ull u; float2 f; } c; c.u = v; return c.f;
}

// ---------------------------------------------------------------------------
// Encoder conv: k=4, s=2, p=1, ReLU.  in NCHW, w OIHW.
// Block 256 thr = 8 warps; warp owns 8 couts (block: 64). Lane owns one
// output column, RPT rows. Input de-interleaved even/odd column planes
// (stride-1 LDS). Weights as LDS.64 cout-pairs; math in fma.rn.f32x2.
// ---------------------------------------------------------------------------
template<int TW, int TH, int CK>
__global__ __launch_bounds__(256, 3)
void conv_enc(const float* __restrict__ in, const float* __restrict__ w,
              const float* __restrict__ bias, float* __restrict__ out,
              int Cin, int Hin, int Win, int Cout)
{
    constexpr int RG  = 32 / TW;
    constexpr int RPT = TH / RG;
    constexpr int IR  = 2 * TH + 2;
    constexpr int HCP = (TW == 16) ? 18 : 33;
    constexpr int TC  = 2 * TW + 2;

    __shared__ float ev_s[CK][IR][HCP];
    __shared__ float od_s[CK][IR][HCP];
    __shared__ __align__(16) float w_s[CK][16][64];

    const int Hout = Hin >> 1, Wout = Win >> 1;
    const int tiles_x = Wout / TW;
    const int tx = blockIdx.x % tiles_x;
    const int ty = blockIdx.x / tiles_x;
    const int oy0 = ty * TH, ox0 = tx * TW;
    const int co0 = blockIdx.y * 64;
    const int b   = blockIdx.z;

    const int tid  = threadIdx.x;
    const int cg   = tid >> 5;
    const int lane = tid & 31;
    const int colx = lane % TW;
    const int rg   = lane / TW;
    const int cg8  = cg * 8;
    const int rbase = 2 * rg * RPT;

    ull acc[RPT][4];                        // 8 couts as 4 packed pairs
    #pragma unroll
    for (int i = 0; i < RPT; i++)
        #pragma unroll
        for (int c = 0; c < 4; c++) acc[i][c] = 0ull;

    const int  iy_org = 2 * oy0 - 1;
    const int  ix_org = 2 * ox0 - 1;
    const long inB = (long)b * Cin * Hin * Win;

    for (int ci0 = 0; ci0 < Cin; ci0 += CK) {
        __syncthreads();
        for (int idx = tid; idx < CK * IR * TC; idx += 256) {
            int j  = idx % TC;
            int r  = (idx / TC) % IR;
            int ci = idx / (TC * IR);
            int iy = iy_org + r, ix = ix_org + j;
            int cig = ci0 + ci;
            float v = 0.f;
            if (cig < Cin && iy >= 0 && iy < Hin && ix >= 0 && ix < Win)
                v = in[inB + ((long)cig * Hin + iy) * Win + ix];
            if (j & 1) od_s[ci][r][j >> 1] = v;
            else       ev_s[ci][r][j >> 1] = v;
        }
        for (int idx = tid; idx < CK * 16 * 64; idx += 256) {
            int cl = idx & 63;
            int t  = (idx >> 6) & 15;
            int ci = idx >> 10;
            int cig = ci0 + ci;
            float v = 0.f;
            if (cig < Cin)
                v = w[((long)(co0 + cl) * Cin + cig) * 16 + t];
            w_s[ci][t][cl] = v;
        }
        __syncthreads();

        #pragma unroll 1
        for (int ci = 0; ci < CK; ci++) {
            #pragma unroll
            for (int q = 0; q < 2; q++) {         // row parity; ky in {q,q+2}
                #pragma unroll
                for (int kx = 0; kx < 4; kx++) {
                    const float* pl = (kx & 1) ? &od_s[ci][0][0] : &ev_s[ci][0][0];
                    const int off = colx + (kx >> 1);
                    const ull* w0 = reinterpret_cast<const ull*>(&w_s[ci][ q      * 4 + kx][cg8]);
                    const ull* w2 = reinterpret_cast<const ull*>(&w_s[ci][(q + 2) * 4 + kx][cg8]);
                    ull u00 = w0[0], u01 = w0[1], u02 = w0[2], u03 = w0[3];
                    ull u20 = w2[0], u21 = w2[1], u22 = w2[2], u23 = w2[3];
                    #pragma unroll
                    for (int j = 0; j <= RPT; j++) {
                        ull aa = pack2(pl[(rbase + 2 * j + q) * HCP + off]);
                        if (j < RPT) {            // ky=q -> row j
                            ffma2(acc[j][0], aa, u00); ffma2(acc[j][1], aa, u01);
                            ffma2(acc[j][2], aa, u02); ffma2(acc[j][3], aa, u03);
                        }
                        if (j > 0) {              // ky=q+2 -> row j-1
                            ffma2(acc[j-1][0], aa, u20); ffma2(acc[j-1][1], aa, u21);
                            ffma2(acc[j-1][2], aa, u22); ffma2(acc[j-1][3], aa, u23);
                        }
                    }
                }
            }
        }
    }

    const long outB = (long)b * Cout * Hout * Wout;
    const int  ox = ox0 + colx;
    #pragma unroll
    for (int p = 0; p < 4; p++) {
        const int co = co0 + cg8 + 2 * p;
        const float bv0 = bias[co], bv1 = bias[co + 1];
        #pragma unroll
        for (int i = 0; i < RPT; i++) {
            const int oy = oy0 + rg * RPT + i;
            float2 v = upk(acc[i][p]);
            out[outB + ((long)co       * Hout + oy) * Wout + ox] = fmaxf(v.x + bv0, 0.f);
            out[outB + ((long)(co + 1) * Hout + oy) * Wout + ox] = fmaxf(v.y + bv1, 0.f);
        }
    }
}

// ---------------------------------------------------------------------------
// ConvTranspose: k=4, s=2, p=1, ReLU. w layout (Cin, Cout, 4, 4).
// Same tiling as R3/R4; math converted to fma.rn.f32x2 (couts as pairs).
// ---------------------------------------------------------------------------
template<int TWI, int CK>
__global__ __launch_bounds__(256)
void convt(const float* __restrict__ in, const float* __restrict__ w,
           const float* __restrict__ bias, float* __restrict__ out,
           int Cin, int Hin, int Win, int Cout)
{
    constexpr int PRT  = 2;
    constexpr int RGI  = 32 / TWI;
    constexpr int BIR  = PRT * RGI;
    constexpr int PIR  = BIR + 2;
    constexpr int PIC  = TWI + 2;
    constexpr int PICP = (TWI == 16) ? 24 : 35;

    __shared__ float in_s[CK][PIR][PICP];
    __shared__ __align__(16) float w_s[CK][16][32];

    const int Hout = Hin * 2, Wout = Win * 2;
    const int colb = Win / TWI;
    const int tx = blockIdx.x % colb;
    const int ry = blockIdx.x / colb;
    const int Rbase = ry * BIR;
    const int c0 = tx * TWI;
    const int co0 = blockIdx.y * 32;
    const int b   = blockIdx.z;

    const int tid  = threadIdx.x;
    const int cg   = tid >> 5;
    const int lane = tid & 31;
    const int cI   = lane % TWI;
    const int rgI  = lane / TWI;
    const int cg4  = cg * 4;
    const int prbase = rgI * PRT;
    const int pcol = cI + 1;

    ull acc[2][2][2][2];                    // [iR][py][px][coutpair]
    #pragma unroll
    for (int i = 0; i < 2; i++)
        #pragma unroll
        for (int p = 0; p < 2; p++)
            #pragma unroll
            for (int q = 0; q < 2; q++)
                #pragma unroll
                for (int c = 0; c < 2; c++) acc[i][p][q][c] = 0ull;

    const long inB = (long)b * Cin * Hin * Win;

    for (int ci0 = 0; ci0 < Cin; ci0 += CK) {
        __syncthreads();
        for (int idx = tid; idx < CK * PIR * PIC; idx += 256) {
            int j  = idx % PIC;
            int pr = (idx / PIC) % PIR;
            int ci = idx / (PIC * PIR);
            int iy = Rbase - 1 + pr, ix = c0 - 1 + j;
            int cig = ci0 + ci;
            float v = 0.f;
            if (cig < Cin && iy >= 0 && iy < Hin && ix >= 0 && ix < Win)
                v = in[inB + ((long)cig * Hin + iy) * Win + ix];
            in_s[ci][pr][j] = v;
        }
        for (int idx = tid; idx < CK * 16 * 32; idx += 256) {
            int cl = idx & 31;
            int t  = (idx >> 5) & 15;
            int ci = idx >> 9;
            int cig = ci0 + ci;
            float v = 0.f;
            if (cig < Cin)
                v = w[((long)cig * Cout + (co0 + cl)) * 16 + t];
            w_s[ci][t][cl] = v;
        }
        __syncthreads();

        #pragma unroll 1
        for (int ci = 0; ci < CK; ci++) {
            #pragma unroll
            for (int px = 0; px < 2; px++) {
                ull wk[4][2][2];            // [ky][kxi][coutpair]
                #pragma unroll
                for (int ky = 0; ky < 4; ky++)
                    #pragma unroll
                    for (int kxi = 0; kxi < 2; kxi++) {
                        const ull* wp = reinterpret_cast<const ull*>(
                            &w_s[ci][ky * 4 + (px ^ 1) + 2 * kxi][cg4]);
                        wk[ky][kxi][0] = wp[0]; wk[ky][kxi][1] = wp[1];
                    }
                const int ca = pcol + px;
                const int cb = pcol + px - 1;
                #pragma unroll
                for (int jr = 0; jr < 4; jr++) {
                    const int pr = prbase + jr;
                    ull a0 = pack2(in_s[ci][pr][ca]);
                    ull a1 = pack2(in_s[ci][pr][cb]);
                    if (jr >= 1 && jr <= 2) {
                        ffma2(acc[jr-1][0][px][0], a0, wk[1][0][0]); ffma2(acc[jr-1][0][px][1], a0, wk[1][0][1]);
                        ffma2(acc[jr-1][0][px][0], a1, wk[1][1][0]); ffma2(acc[jr-1][0][px][1], a1, wk[1][1][1]);
                        ffma2(acc[jr-1][1][px][0], a0, wk[2][0][0]); ffma2(acc[jr-1][1][px][1], a0, wk[2][0][1]);
                        ffma2(acc[jr-1][1][px][0], a1, wk[2][1][0]); ffma2(acc[jr-1][1][px][1], a1, wk[2][1][1]);
                    }
                    if (jr < 2) {
                        ffma2(acc[jr][0][px][0], a0, wk[3][0][0]); ffma2(acc[jr][0][px][1], a0, wk[3][0][1]);
                        ffma2(acc[jr][0][px][0], a1, wk[3][1][0]); ffma2(acc[jr][0][px][1], a1, wk[3][1][1]);
                    }
                    if (jr >= 2) {
                        ffma2(acc[jr-2][1][px][0], a0, wk[0][0][0]); ffma2(acc[jr-2][1][px][1], a0, wk[0][0][1]);
                        ffma2(acc[jr-2][1][px][0], a1, wk[0][1][0]); ffma2(acc[jr-2][1][px][1], a1, wk[0][1][1]);
                    }
                }
            }
        }
    }

    const long outB = (long)b * Cout * Hout * Wout;
    const int  oxp = 2 * (c0 + cI);
    #pragma unroll
    for (int cp = 0; cp < 2; cp++) {
        #pragma unroll
        for (int h = 0; h < 2; h++) {
            const int co = co0 + cg4 + 2 * cp + h;
            const float bv = bias[co];
            #pragma unroll
            for (int iR = 0; iR < 2; iR++) {
                #pragma unroll
                for (int py = 0; py < 2; py++) {
                    const int oy = 2 * (Rbase + prbase + iR) + py;
                    float2 v0 = upk(acc[iR][py][0][cp]);
                    float2 v1 = upk(acc[iR][py][1][cp]);
                    float2 v;
                    v.x = fmaxf((h ? v0.y : v0.x) + bv, 0.f);
                    v.y = fmaxf((h ? v1.y : v1.x) + bv, 0.f);
                    *reinterpret_cast<float2*>(&out[outB + ((long)co * Hout + oy) * Wout + oxp]) = v;
                }
            }
        }
    }
}

// ---------------------------------------------------------------------------
// Final ConvT layer: Cin=32, Cout=3, tanh.
// ---------------------------------------------------------------------------
__global__ __launch_bounds__(256)
void convt_final_kernel(const float* __restrict__ in, const float* __restrict__ w,
                        const float* __restrict__ bias, float* __restrict__ out)
{
    const int Cin = 32, Hin = 128, Win = 128, Hout = 256, Wout = 256;
    __shared__ float in_s[32][10][11];
    __shared__ float w_s[32][3][16];

    const int tid = threadIdx.x;
    const int b = blockIdx.z;
    const int tx = blockIdx.x & 15;
    const int ty = blockIdx.x >> 4;
    const int oy0 = ty * 16, ox0 = tx * 16;
    const int iyb = oy0 / 2 - 1, ixb = ox0 / 2 - 1;

    for (int i = tid; i < 32 * 3 * 16; i += 256)
        ((float*)w_s)[i] = w[i];
    const float* inb = in + (long)b * Cin * Hin * Win;
    for (int idx = tid; idx < 3200; idx += 256) {
        int c  = idx % 10;
        int r  = (idx / 10) % 10;
        int ci = idx / 100;
        int iy = iyb + r, ix = ixb + c;
        float v = 0.f;
        if (iy >= 0 && iy < Hin && ix >= 0 && ix < Win)
            v = inb[((long)ci * Hin + iy) * Win + ix];
        in_s[ci][r][c] = v;
    }
    __syncthreads();

    const int ox = ox0 + (tid & 15);
    const int oy = oy0 + (tid >> 4);
    const int ky0 = (oy + 1) & 1;
    const int kx0 = (ox + 1) & 1;

    float a0 = bias[0], a1 = bias[1], a2 = bias[2];
    #pragma unroll
    for (int kyi = 0; kyi < 2; kyi++) {
        #pragma unroll
        for (int kxi = 0; kxi < 2; kxi++) {
            const int ky = ky0 + 2 * kyi, kx = kx0 + 2 * kxi;
            const int pr = (oy + 1 - ky) / 2 - iyb;
            const int pc = (ox + 1 - kx) / 2 - ixb;
            const int t = ky * 4 + kx;
            #pragma unroll 8
            for (int ci = 0; ci < 32; ci++) {
                float v = in_s[ci][pr][pc];
                a0 += v * w_s[ci][0][t];
                a1 += v * w_s[ci][1][t];
                a2 += v * w_s[ci][2][t];
            }
        }
    }
    const long o = (long)b * 3 * Hout * Wout + (long)oy * Wout + ox;
    out[o]                    = tanhf(a0);
    out[o + (long)Hout*Wout]  = tanhf(a1);
    out[o + 2L*Hout*Wout]     = tanhf(a2);
}

// ---------------------------------------------------------------------------
// Quantizer
// ---------------------------------------------------------------------------
__global__ void e2_kernel(const float* __restrict__ embed, float* __restrict__ e2)
{
    int k = blockIdx.x * blockDim.x + threadIdx.x;
    if (k >= 1024) return;
    const float* e = embed + (long)k * 512;
    float s = 0.f;
    #pragma unroll 4
    for (int d = 0; d < 512; d++) { float v = e[d]; s += v * v; }
    e2[k] = s;
}

__global__ __launch_bounds__(128)
void argmin_kernel(const float* __restrict__ z, const float* __restrict__ embed,
                   const float* __restrict__ e2, int* __restrict__ idx_out)
{
    __shared__ __align__(16) float z_s[512][8];
    __shared__ float rv[8][128];
    __shared__ int   ri[8][128];
    const int tid = threadIdx.x;
    const int n0 = blockIdx.x * 8;
    const int b = n0 >> 8;
    const int pix0 = n0 & 255;
    const float* zb = z + (long)b * 512 * 256 + pix0;

    for (int i = tid; i < 512 * 8; i += 128) {
        int d = i >> 3, nl = i & 7;
        z_s[d][nl] = zb[(long)d * 256 + nl];
    }
    __syncthreads();

    float bv[8]; int bi[8];
    #pragma unroll
    for (int nl = 0; nl < 8; nl++) { bv[nl] = 3.4e38f; bi[nl] = 0; }

    for (int k = tid; k < 1024; k += 128) {
        const float* e = embed + (long)k * 512;
        ull dp[4];
        #pragma unroll
        for (int h = 0; h < 4; h++) dp[h] = 0ull;
        #pragma unroll 4
        for (int d = 0; d < 512; d++) {
            ull ev2 = pack2(e[d]);
            const ull* zp = reinterpret_cast<const ull*>(&z_s[d][0]);
            ffma2(dp[0], ev2, zp[0]); ffma2(dp[1], ev2, zp[1]);
            ffma2(dp[2], ev2, zp[2]); ffma2(dp[3], ev2, zp[3]);
        }
        float c = e2[k];
        #pragma unroll
        for (int h = 0; h < 4; h++) {
            float2 dv = upk(dp[h]);
            float dist0 = c - 2.f * dv.x;
            float dist1 = c - 2.f * dv.y;
            if (dist0 < bv[2*h])   { bv[2*h]   = dist0; bi[2*h]   = k; }
            if (dist1 < bv[2*h+1]) { bv[2*h+1] = dist1; bi[2*h+1] = k; }
        }
    }
    #pragma unroll
    for (int nl = 0; nl < 8; nl++) { rv[nl][tid] = bv[nl]; ri[nl][tid] = bi[nl]; }
    __syncthreads();
    if (tid < 8) {
        float best = rv[tid][0]; int besti = ri[tid][0];
        for (int j = 1; j < 128; j++) {
            float v = rv[tid][j]; int ii = ri[tid][j];
            if (v < best || (v == best && ii < besti)) { best = v; besti = ii; }
        }
        idx_out[n0 + tid] = besti;
    }
}

__global__ void gather_kernel(const int* __restrict__ idx, const float* __restrict__ embed,
                              float* __restrict__ zq)
{
    const int n = blockIdx.x;
    const int b = n >> 8, pix = n & 255;
    const float* e = embed + (long)idx[n] * 512;
    float* o = zq + (long)b * 512 * 256 + pix;
    for (int d = threadIdx.x; d < 512; d += 256)
        o[(long)d * 256] = e[d];
}

// ---------------------------------------------------------------------------
// Launch
// ---------------------------------------------------------------------------
extern "C" void kernel_launch(void* const* d_in, const int* in_sizes, int n_in,
                              void* d_out, int out_size)
{
    const float* x     = (const float*)d_in[0];
    const float* ew1   = (const float*)d_in[1];
    const float* eb1   = (const float*)d_in[2];
    const float* ew2   = (const float*)d_in[3];
    const float* eb2   = (const float*)d_in[4];
    const float* ew3   = (const float*)d_in[5];
    const float* eb3   = (const float*)d_in[6];
    const float* ew4   = (const float*)d_in[7];
    const float* eb4   = (const float*)d_in[8];
    const float* dw1   = (const float*)d_in[9];
    const float* db1   = (const float*)d_in[10];
    const float* dw2   = (const float*)d_in[11];
    const float* db2   = (const float*)d_in[12];
    const float* dw3   = (const float*)d_in[13];
    const float* db3   = (const float*)d_in[14];
    const float* dw4   = (const float*)d_in[15];
    const float* db4   = (const float*)d_in[16];
    const float* embed = (const float*)d_in[17];
    float* out = (float*)d_out;

    float *A, *B, *e2p; int* idxp;
    cudaGetSymbolAddress((void**)&A,    g_bufA);
    cudaGetSymbolAddress((void**)&B,    g_bufB);
    cudaGetSymbolAddress((void**)&e2p,  g_e2);
    cudaGetSymbolAddress((void**)&idxp, g_idx);

    const int NB = 32;

    // ---- encoder (64 couts per block) ----
    conv_enc<32,4,4><<<dim3(128, 1, NB), 256>>>(x,  ew1, eb1, A, 3,   256, 256, 64);
    conv_enc<32,4,4><<<dim3(32, 2, NB), 256>>>(A,  ew2, eb2, B, 64,  128, 128, 128);
    conv_enc<32,4,4><<<dim3(8,  4, NB), 256>>>(B,  ew3, eb3, A, 128, 64,  64,  256);
    conv_enc<16,8,4><<<dim3(2,  8, NB), 256>>>(A,  ew4, eb4, B, 256, 32,  32,  512);

    // ---- quantizer ----
    e2_kernel<<<4, 256>>>(embed, e2p);
    argmin_kernel<<<1024, 128>>>(B, embed, e2p, idxp);
    gather_kernel<<<8192, 256>>>(idxp, embed, A);          // zq in A

    // ---- decoder ----
    convt<16,8><<<dim3(4,  4, NB), 256>>>(A, dw1, db1, B, 512, 16,  16,  128);
    convt<32,8><<<dim3(16, 2, NB), 256>>>(B, dw2, db2, A, 128, 32,  32,  64);
    convt<32,8><<<dim3(64, 1, NB), 256>>>(A, dw3, db3, B, 64,  64,  64,  32);
    convt_final_kernel<<<dim3(256, 1, NB), 256>>>(B, dw4, db4, out);
}

// round 6
// speedup vs baseline: 1.4564x; 1.3136x over previous
#include <cuda_runtime.h>
#include <cuda_bf16.h>
#include <math.h>

typedef unsigned int u32;
typedef unsigned long long ull;

// ---------------------------------------------------------------------------
// Scratch (device globals; no allocation anywhere)
// ---------------------------------------------------------------------------
static __device__ float g_bufA[33554432];   // 134 MB
static __device__ float g_bufB[16777216];   //  67 MB
static __device__ int   g_idx[8192];
static __device__ float g_e2[1024];
static __device__ u32   g_wt[2760704];      // transposed bf16x2 hi/lo weights

// packed f32x2 helpers (decoder scalar path)
__device__ __forceinline__ void ffma2(ull& d, ull a, ull b) {
    asm("fma.rn.f32x2 %0, %1, %2, %0;" : "+l"(d) : "l"(a), "l"(b));
}
__device__ __forceinline__ ull pack2(float a) {
    ull r; unsigned int ai = __float_as_uint(a);
    asm("mov.b64 %0, {%1, %1};" : "=l"(r) : "r"(ai));
    return r;
}
__device__ __forceinline__ float2 upk(ull v) {
    union { ull u; float2 f; } c; c.u = v; return c.f;
}

// bf16x2 pack of two floats (v0 -> low half = even K element)
__device__ __forceinline__ u32 packbf(float v0, float v1) {
    __nv_bfloat162 t = __floats2bfloat162_rn(v0, v1);
    u32 r; memcpy(&r, &t, 4); return r;
}

// m16n8k8 row.col bf16 MMA, fp32 accum
__device__ __forceinline__ void mma8(float* c, u32 a0, u32 a1, u32 b) {
    asm("mma.sync.aligned.m16n8k8.row.col.f32.bf16.bf16.f32 "
        "{%0,%1,%2,%3}, {%4,%5}, {%6}, {%0,%1,%2,%3};"
        : "+f"(c[0]), "+f"(c[1]), "+f"(c[2]), "+f"(c[3])
        : "r"(a0), "r"(a1), "r"(b));
}

// ---------------------------------------------------------------------------
// Weight transpose: OIHW fp32 -> [t][cinpair][cout] bf16x2 {hi then lo}
// dst[idx] with idx = (t*CPG + cp)*Cout + co ; lo at dst + 16*CPG*Cout
// ---------------------------------------------------------------------------
__global__ void wtrans_kernel(const float* __restrict__ w, u32* __restrict__ dst,
                              int Cin, int Cout, int CPG)
{
    const int S = 16 * CPG * Cout;
    int idx = blockIdx.x * 256 + threadIdx.x;
    if (idx >= S) return;
    int co = idx % Cout;
    int rest = idx / Cout;
    int cp = rest % CPG;
    int t  = rest / CPG;
    int ci0 = 2 * cp;
    float v0 = (ci0     < Cin) ? w[((long)co * Cin + ci0    ) * 16 + t] : 0.f;
    float v1 = (ci0 + 1 < Cin) ? w[((long)co * Cin + ci0 + 1) * 16 + t] : 0.f;
    __nv_bfloat162 h = __floats2bfloat162_rn(v0, v1);
    float r0 = v0 - __bfloat162float(h.x);
    float r1 = v1 - __bfloat162float(h.y);
    dst[idx]     = packbf(v0, v1);          // hi (RN of v)
    dst[S + idx] = packbf(r0, r1);          // lo (residual)
}

// ---------------------------------------------------------------------------
// Encoder conv via implicit GEMM, split-bf16 m16n8k8 MMA.
// k=4,s=2,p=1,ReLU. Block: 256 thr = 8 warps = 4 wm (oy rows) x 2 wn (32 couts).
// Block tile: 4 oy x 16 ox spatial (M=64) x 64 couts (N). K = Cin*16 taps,
// chunked 8 cins at a time (4 cin-pairs = one k8 fragment).
// A: smem even/odd x-planes of bf16x2 cin-pairs -> 1 conflict-free LDS.32/frag.
// B: smem [t][cp][72-padded couts] -> conflict-free (8a+b) LDS.32/frag.
// ---------------------------------------------------------------------------
__global__ __launch_bounds__(256)
void conv_enc_mma(const float* __restrict__ in, const u32* __restrict__ wt,
                  const float* __restrict__ bias, float* __restrict__ out,
                  int Cin, int Hin, int Win, int Cout, int CPG)
{
    __shared__ u32 a_s[2][2][10][17][4];   // [hi/lo][xpar][y][m][cp]  10880 B
    __shared__ u32 w_sm[2][16][4][72];     // [hi/lo][t][cp][co pad72] 36864 B

    const int Hout = Hin >> 1, Wout = Win >> 1;
    const int tiles_x = Wout >> 4;
    const int tx = blockIdx.x % tiles_x;
    const int ty = blockIdx.x / tiles_x;
    const int OX0 = tx * 16, OY0 = ty * 4;
    const int co0 = blockIdx.y * 64;
    const int b   = blockIdx.z;

    const int tid  = threadIdx.x;
    const int wid  = tid >> 5;
    const int lane = tid & 31;
    const int wm   = wid & 3;          // oy row
    const int wn   = wid >> 2;         // 32-cout half
    const int l4   = lane >> 2;
    const int lm4  = lane & 3;

    const u32* wt_lo = wt + 16 * CPG * Cout;

    float acc[4][4];
    #pragma unroll
    for (int nf = 0; nf < 4; nf++)
        #pragma unroll
        for (int c = 0; c < 4; c++) acc[nf][c] = 0.f;

    const long inB = (long)b * Cin * Hin * Win;
    const int nChunk = CPG >> 2;       // 8 cins per chunk

    #pragma unroll 1
    for (int cic = 0; cic < nChunk; cic++) {
        __syncthreads();
        // ---- stage activations: (y 10) x (xs 34) x (cp 4) words, hi+lo ----
        for (int idx = tid; idx < 10 * 34 * 4; idx += 256) {
            int xs = idx % 34;
            int cp = (idx / 34) & 3;
            int y  = idx / 136;
            int ci0 = cic * 8 + 2 * cp;
            int gy = 2 * OY0 - 1 + y;
            int gx = 2 * OX0 - 1 + xs;
            float v0 = 0.f, v1 = 0.f;
            if (gy >= 0 && gy < Hin && gx >= 0 && gx < Win) {
                if (ci0     < Cin) v0 = in[inB + ((long)ci0       * Hin + gy) * Win + gx];
                if (ci0 + 1 < Cin) v1 = in[inB + ((long)(ci0 + 1) * Hin + gy) * Win + gx];
            }
            __nv_bfloat162 h = __floats2bfloat162_rn(v0, v1);
            float r0 = v0 - __bfloat162float(h.x);
            float r1 = v1 - __bfloat162float(h.y);
            a_s[0][xs & 1][y][xs >> 1][cp] = packbf(v0, v1);
            a_s[1][xs & 1][y][xs >> 1][cp] = packbf(r0, r1);
        }
        // ---- stage weights: [t 16][cpl 4][co 64] words, hi+lo ----
        for (int idx = tid; idx < 16 * 4 * 64; idx += 256) {
            int co  = idx & 63;
            int cpl = (idx >> 6) & 3;
            int t   = idx >> 8;
            long src = ((long)t * CPG + cic * 4 + cpl) * Cout + co0 + co;
            w_sm[0][t][cpl][co] = wt[src];
            w_sm[1][t][cpl][co] = wt_lo[src];
        }
        __syncthreads();

        // ---- compute: 16 taps x (A 4 LDS + B 8 LDS + 12 MMA) ----
        #pragma unroll
        for (int ky = 0; ky < 4; ky++) {
            const int y = 2 * wm + ky;
            #pragma unroll
            for (int kx = 0; kx < 4; kx++) {
                const int par = kx & 1;
                const int md  = kx >> 1;
                const int t   = ky * 4 + kx;
                u32 ah0 = a_s[0][par][y][l4 + md][lm4];
                u32 ah1 = a_s[0][par][y][l4 + md + 8][lm4];
                u32 al0 = a_s[1][par][y][l4 + md][lm4];
                u32 al1 = a_s[1][par][y][l4 + md + 8][lm4];
                #pragma unroll
                for (int nf = 0; nf < 4; nf++) {
                    const int coi = wn * 32 + nf * 8 + l4;
                    u32 bh = w_sm[0][t][lm4][coi];
                    u32 bl = w_sm[1][t][lm4][coi];
                    mma8(acc[nf], ah0, ah1, bh);   // hi*hi
                    mma8(acc[nf], ah0, ah1, bl);   // hi*lo
                    mma8(acc[nf], al0, al1, bh);   // lo*hi
                }
            }
        }
    }

    // ---- epilogue: bias + ReLU ----
    const long outB = (long)b * Cout * Hout * Wout;
    const int oy = OY0 + wm;
    const int ox0l = OX0 + l4;
    #pragma unroll
    for (int nf = 0; nf < 4; nf++) {
        const int cob = co0 + wn * 32 + nf * 8 + 2 * lm4;
        const float b0 = bias[cob], b1 = bias[cob + 1];
        float* o0 = &out[outB + ((long)cob       * Hout + oy) * Wout];
        float* o1 = &out[outB + ((long)(cob + 1) * Hout + oy) * Wout];
        o0[ox0l]     = fmaxf(acc[nf][0] + b0, 0.f);
        o1[ox0l]     = fmaxf(acc[nf][1] + b1, 0.f);
        o0[ox0l + 8] = fmaxf(acc[nf][2] + b0, 0.f);
        o1[ox0l + 8] = fmaxf(acc[nf][3] + b1, 0.f);
    }
}

// ---------------------------------------------------------------------------
// ConvTranspose: k=4, s=2, p=1, ReLU (scalar f32x2 path, unchanged from R5)
// ---------------------------------------------------------------------------
template<int TWI, int CK>
__global__ __launch_bounds__(256)
void convt(const float* __restrict__ in, const float* __restrict__ w,
           const float* __restrict__ bias, float* __restrict__ out,
           int Cin, int Hin, int Win, int Cout)
{
    constexpr int PRT  = 2;
    constexpr int RGI  = 32 / TWI;
    constexpr int BIR  = PRT * RGI;
    constexpr int PIR  = BIR + 2;
    constexpr int PIC  = TWI + 2;
    constexpr int PICP = (TWI == 16) ? 24 : 35;

    __shared__ float in_s[CK][PIR][PICP];
    __shared__ __align__(16) float w_s[CK][16][32];

    const int Hout = Hin * 2, Wout = Win * 2;
    const int colb = Win / TWI;
    const int tx = blockIdx.x % colb;
    const int ry = blockIdx.x / colb;
    const int Rbase = ry * BIR;
    const int c0 = tx * TWI;
    const int co0 = blockIdx.y * 32;
    const int b   = blockIdx.z;

    const int tid  = threadIdx.x;
    const int cg   = tid >> 5;
    const int lane = tid & 31;
    const int cI   = lane % TWI;
    const int rgI  = lane / TWI;
    const int cg4  = cg * 4;
    const int prbase = rgI * PRT;
    const int pcol = cI + 1;

    ull acc[2][2][2][2];
    #pragma unroll
    for (int i = 0; i < 2; i++)
        #pragma unroll
        for (int p = 0; p < 2; p++)
            #pragma unroll
            for (int q = 0; q < 2; q++)
                #pragma unroll
                for (int c = 0; c < 2; c++) acc[i][p][q][c] = 0ull;

    const long inB = (long)b * Cin * Hin * Win;

    for (int ci0 = 0; ci0 < Cin; ci0 += CK) {
        __syncthreads();
        for (int idx = tid; idx < CK * PIR * PIC; idx += 256) {
            int j  = idx % PIC;
            int pr = (idx / PIC) % PIR;
            int ci = idx / (PIC * PIR);
            int iy = Rbase - 1 + pr, ix = c0 - 1 + j;
            int cig = ci0 + ci;
            float v = 0.f;
            if (cig < Cin && iy >= 0 && iy < Hin && ix >= 0 && ix < Win)
                v = in[inB + ((long)cig * Hin + iy) * Win + ix];
            in_s[ci][pr][j] = v;
        }
        for (int idx = tid; idx < CK * 16 * 32; idx += 256) {
            int cl = idx & 31;
            int t  = (idx >> 5) & 15;
            int ci = idx >> 9;
            int cig = ci0 + ci;
            float v = 0.f;
            if (cig < Cin)
                v = w[((long)cig * Cout + (co0 + cl)) * 16 + t];
            w_s[ci][t][cl] = v;
        }
        __syncthreads();

        #pragma unroll 1
        for (int ci = 0; ci < CK; ci++) {
            #pragma unroll
            for (int px = 0; px < 2; px++) {
                ull wk[4][2][2];
                #pragma unroll
                for (int ky = 0; ky < 4; ky++)
                    #pragma unroll
                    for (int kxi = 0; kxi < 2; kxi++) {
                        const ull* wp = reinterpret_cast<const ull*>(
                            &w_s[ci][ky * 4 + (px ^ 1) + 2 * kxi][cg4]);
                        wk[ky][kxi][0] = wp[0]; wk[ky][kxi][1] = wp[1];
                    }
                const int ca = pcol + px;
                const int cb = pcol + px - 1;
                #pragma unroll
                for (int jr = 0; jr < 4; jr++) {
                    const int pr = prbase + jr;
                    ull a0 = pack2(in_s[ci][pr][ca]);
                    ull a1 = pack2(in_s[ci][pr][cb]);
                    if (jr >= 1 && jr <= 2) {
                        ffma2(acc[jr-1][0][px][0], a0, wk[1][0][0]); ffma2(acc[jr-1][0][px][1], a0, wk[1][0][1]);
                        ffma2(acc[jr-1][0][px][0], a1, wk[1][1][0]); ffma2(acc[jr-1][0][px][1], a1, wk[1][1][1]);
                        ffma2(acc[jr-1][1][px][0], a0, wk[2][0][0]); ffma2(acc[jr-1][1][px][1], a0, wk[2][0][1]);
                        ffma2(acc[jr-1][1][px][0], a1, wk[2][1][0]); ffma2(acc[jr-1][1][px][1], a1, wk[2][1][1]);
                    }
                    if (jr < 2) {
                        ffma2(acc[jr][0][px][0], a0, wk[3][0][0]); ffma2(acc[jr][0][px][1], a0, wk[3][0][1]);
                        ffma2(acc[jr][0][px][0], a1, wk[3][1][0]); ffma2(acc[jr][0][px][1], a1, wk[3][1][1]);
                    }
                    if (jr >= 2) {
                        ffma2(acc[jr-2][1][px][0], a0, wk[0][0][0]); ffma2(acc[jr-2][1][px][1], a0, wk[0][0][1]);
                        ffma2(acc[jr-2][1][px][0], a1, wk[0][1][0]); ffma2(acc[jr-2][1][px][1], a1, wk[0][1][1]);
                    }
                }
            }
        }
    }

    const long outB = (long)b * Cout * Hout * Wout;
    const int  oxp = 2 * (c0 + cI);
    #pragma unroll
    for (int cp = 0; cp < 2; cp++) {
        #pragma unroll
        for (int h = 0; h < 2; h++) {
            const int co = co0 + cg4 + 2 * cp + h;
            const float bv = bias[co];
            #pragma unroll
            for (int iR = 0; iR < 2; iR++) {
                #pragma unroll
                for (int py = 0; py < 2; py++) {
                    const int oy = 2 * (Rbase + prbase + iR) + py;
                    float2 v0 = upk(acc[iR][py][0][cp]);
                    float2 v1 = upk(acc[iR][py][1][cp]);
                    float2 v;
                    v.x = fmaxf((h ? v0.y : v0.x) + bv, 0.f);
                    v.y = fmaxf((h ? v1.y : v1.x) + bv, 0.f);
                    *reinterpret_cast<float2*>(&out[outB + ((long)co * Hout + oy) * Wout + oxp]) = v;
                }
            }
        }
    }
}

// ---------------------------------------------------------------------------
// Final ConvT layer: Cin=32, Cout=3, tanh.
// ---------------------------------------------------------------------------
__global__ __launch_bounds__(256)
void convt_final_kernel(const float* __restrict__ in, const float* __restrict__ w,
                        const float* __restrict__ bias, float* __restrict__ out)
{
    const int Cin = 32, Hin = 128, Win = 128, Hout = 256, Wout = 256;
    __shared__ float in_s[32][10][11];
    __shared__ float w_s[32][3][16];

    const int tid = threadIdx.x;
    const int b = blockIdx.z;
    const int tx = blockIdx.x & 15;
    const int ty = blockIdx.x >> 4;
    const int oy0 = ty * 16, ox0 = tx * 16;
    const int iyb = oy0 / 2 - 1, ixb = ox0 / 2 - 1;

    for (int i = tid; i < 32 * 3 * 16; i += 256)
        ((float*)w_s)[i] = w[i];
    const float* inb = in + (long)b * Cin * Hin * Win;
    for (int idx = tid; idx < 3200; idx += 256) {
        int c  = idx % 10;
        int r  = (idx / 10) % 10;
        int ci = idx / 100;
        int iy = iyb + r, ix = ixb + c;
        float v = 0.f;
        if (iy >= 0 && iy < Hin && ix >= 0 && ix < Win)
            v = inb[((long)ci * Hin + iy) * Win + ix];
        in_s[ci][r][c] = v;
    }
    __syncthreads();

    const int ox = ox0 + (tid & 15);
    const int oy = oy0 + (tid >> 4);
    const int ky0 = (oy + 1) & 1;
    const int kx0 = (ox + 1) & 1;

    float a0 = bias[0], a1 = bias[1], a2 = bias[2];
    #pragma unroll
    for (int kyi = 0; kyi < 2; kyi++) {
        #pragma unroll
        for (int kxi = 0; kxi < 2; kxi++) {
            const int ky = ky0 + 2 * kyi, kx = kx0 + 2 * kxi;
            const int pr = (oy + 1 - ky) / 2 - iyb;
            const int pc = (ox + 1 - kx) / 2 - ixb;
            const int t = ky * 4 + kx;
            #pragma unroll 8
            for (int ci = 0; ci < 32; ci++) {
                float v = in_s[ci][pr][pc];
                a0 += v * w_s[ci][0][t];
                a1 += v * w_s[ci][1][t];
                a2 += v * w_s[ci][2][t];
            }
        }
    }
    const long o = (long)b * 3 * Hout * Wout + (long)oy * Wout + ox;
    out[o]                    = tanhf(a0);
    out[o + (long)Hout*Wout]  = tanhf(a1);
    out[o + 2L*Hout*Wout]     = tanhf(a2);
}

// ---------------------------------------------------------------------------
// Quantizer
// ---------------------------------------------------------------------------
__global__ void e2_kernel(const float* __restrict__ embed, float* __restrict__ e2)
{
    int k = blockIdx.x * blockDim.x + threadIdx.x;
    if (k >= 1024) return;
    const float* e = embed + (long)k * 512;
    float s = 0.f;
    #pragma unroll 4
    for (int d = 0; d < 512; d++) { float v = e[d]; s += v * v; }
    e2[k] = s;
}

__global__ __launch_bounds__(128)
void argmin_kernel(const float* __restrict__ z, const float* __restrict__ embed,
                   const float* __restrict__ e2, int* __restrict__ idx_out)
{
    __shared__ __align__(16) float z_s[512][8];
    __shared__ float rv[8][128];
    __shared__ int   ri[8][128];
    const int tid = threadIdx.x;
    const int n0 = blockIdx.x * 8;
    const int b = n0 >> 8;
    const int pix0 = n0 & 255;
    const float* zb = z + (long)b * 512 * 256 + pix0;

    for (int i = tid; i < 512 * 8; i += 128) {
        int d = i >> 3, nl = i & 7;
        z_s[d][nl] = zb[(long)d * 256 + nl];
    }
    __syncthreads();

    float bv[8]; int bi[8];
    #pragma unroll
    for (int nl = 0; nl < 8; nl++) { bv[nl] = 3.4e38f; bi[nl] = 0; }

    for (int k = tid; k < 1024; k += 128) {
        const float* e = embed + (long)k * 512;
        ull dp[4];
        #pragma unroll
        for (int h = 0; h < 4; h++) dp[h] = 0ull;
        #pragma unroll 4
        for (int d = 0; d < 512; d++) {
            ull ev2 = pack2(e[d]);
            const ull* zp = reinterpret_cast<const ull*>(&z_s[d][0]);
            ffma2(dp[0], ev2, zp[0]); ffma2(dp[1], ev2, zp[1]);
            ffma2(dp[2], ev2, zp[2]); ffma2(dp[3], ev2, zp[3]);
        }
        float c = e2[k];
        #pragma unroll
        for (int h = 0; h < 4; h++) {
            float2 dv = upk(dp[h]);
            float dist0 = c - 2.f * dv.x;
            float dist1 = c - 2.f * dv.y;
            if (dist0 < bv[2*h])   { bv[2*h]   = dist0; bi[2*h]   = k; }
            if (dist1 < bv[2*h+1]) { bv[2*h+1] = dist1; bi[2*h+1] = k; }
        }
    }
    #pragma unroll
    for (int nl = 0; nl < 8; nl++) { rv[nl][tid] = bv[nl]; ri[nl][tid] = bi[nl]; }
    __syncthreads();
    if (tid < 8) {
        float best = rv[tid][0]; int besti = ri[tid][0];
        for (int j = 1; j < 128; j++) {
            float v = rv[tid][j]; int ii = ri[tid][j];
            if (v < best || (v == best && ii < besti)) { best = v; besti = ii; }
        }
        idx_out[n0 + tid] = besti;
    }
}

__global__ void gather_kernel(const int* __restrict__ idx, const float* __restrict__ embed,
                              float* __restrict__ zq)
{
    const int n = blockIdx.x;
    const int b = n >> 8, pix = n & 255;
    const float* e = embed + (long)idx[n] * 512;
    float* o = zq + (long)b * 512 * 256 + pix;
    for (int d = threadIdx.x; d < 512; d += 256)
        o[(long)d * 256] = e[d];
}

// ---------------------------------------------------------------------------
// Launch
// ---------------------------------------------------------------------------
extern "C" void kernel_launch(void* const* d_in, const int* in_sizes, int n_in,
                              void* d_out, int out_size)
{
    const float* x     = (const float*)d_in[0];
    const float* ew1   = (const float*)d_in[1];
    const float* eb1   = (const float*)d_in[2];
    const float* ew2   = (const float*)d_in[3];
    const float* eb2   = (const float*)d_in[4];
    const float* ew3   = (const float*)d_in[5];
    const float* eb3   = (const float*)d_in[6];
    const float* ew4   = (const float*)d_in[7];
    const float* eb4   = (const float*)d_in[8];
    const float* dw1   = (const float*)d_in[9];
    const float* db1   = (const float*)d_in[10];
    const float* dw2   = (const float*)d_in[11];
    const float* db2   = (const float*)d_in[12];
    const float* dw3   = (const float*)d_in[13];
    const float* db3   = (const float*)d_in[14];
    const float* dw4   = (const float*)d_in[15];
    const float* db4   = (const float*)d_in[16];
    const float* embed = (const float*)d_in[17];
    float* out = (float*)d_out;

    float *A, *B, *e2p; int* idxp; u32* wtp;
    cudaGetSymbolAddress((void**)&A,    g_bufA);
    cudaGetSymbolAddress((void**)&B,    g_bufB);
    cudaGetSymbolAddress((void**)&e2p,  g_e2);
    cudaGetSymbolAddress((void**)&idxp, g_idx);
    cudaGetSymbolAddress((void**)&wtp,  g_wt);

    const int NB = 32;
    // g_wt offsets (u32 words): layer i hi array at Oi, lo at Oi + 16*CPG*Cout
    u32* w1t = wtp;              // S1 = 16*4*64    = 4096   (x2)
    u32* w2t = wtp + 8192;       // S2 = 16*32*128  = 65536  (x2)
    u32* w3t = wtp + 139264;     // S3 = 16*64*256  = 262144 (x2)
    u32* w4t = wtp + 663552;     // S4 = 16*128*512 = 1048576(x2)

    // ---- weight transposes (cheap, every call; deterministic) ----
    wtrans_kernel<<<16,   256>>>(ew1, w1t, 3,   64,  4);
    wtrans_kernel<<<256,  256>>>(ew2, w2t, 64,  128, 32);
    wtrans_kernel<<<1024, 256>>>(ew3, w3t, 128, 256, 64);
    wtrans_kernel<<<4096, 256>>>(ew4, w4t, 256, 512, 128);

    // ---- encoder (tensor-core implicit GEMM) ----
    // tiles = (Wout/16)*(Hout/4), grid.y = Cout/64
    conv_enc_mma<<<dim3(256, 1, NB), 256>>>(x, w1t, eb1, A, 3,   256, 256, 64,  4);
    conv_enc_mma<<<dim3(64,  2, NB), 256>>>(A, w2t, eb2, B, 64,  128, 128, 128, 32);
    conv_enc_mma<<<dim3(16,  4, NB), 256>>>(B, w3t, eb3, A, 128, 64,  64,  256, 64);
    conv_enc_mma<<<dim3(4,   8, NB), 256>>>(A, w4t, eb4, B, 256, 32,  32,  512, 128);

    // ---- quantizer ----
    e2_kernel<<<4, 256>>>(embed, e2p);
    argmin_kernel<<<1024, 128>>>(B, embed, e2p, idxp);
    gather_kernel<<<8192, 256>>>(idxp, embed, A);          // zq in A

    // ---- decoder ----
    convt<16,8><<<dim3(4,  4, NB), 256>>>(A, dw1, db1, B, 512, 16,  16,  128);
    convt<32,8><<<dim3(16, 2, NB), 256>>>(B, dw2, db2, A, 128, 32,  32,  64);
    convt<32,8><<<dim3(64, 1, NB), 256>>>(A, dw3, db3, B, 64,  64,  64,  32);
    convt_final_kernel<<<dim3(256, 1, NB), 256>>>(B, dw4, db4, out);
}

// round 7
// speedup vs baseline: 1.5261x; 1.0478x over previous
#include <cuda_runtime.h>
#include <cuda_bf16.h>
#include <math.h>

typedef unsigned int u32;
typedef unsigned long long ull;

// ---------------------------------------------------------------------------
// Scratch (device globals; no allocation anywhere)
// ---------------------------------------------------------------------------
static __device__ float g_bufA[33554432];   // 134 MB
static __device__ float g_bufB[16777216];   //  67 MB
static __device__ int   g_idx[8192];
static __device__ float g_e2[1024];
static __device__ u32   g_wt[4005888];      // transposed bf16x2 hi/lo weights (enc+dec)

// packed f32x2 helpers (scalar paths)
__device__ __forceinline__ void ffma2(ull& d, ull a, ull b) {
    asm("fma.rn.f32x2 %0, %1, %2, %0;" : "+l"(d) : "l"(a), "l"(b));
}
__device__ __forceinline__ ull pack2(float a) {
    ull r; unsigned int ai = __float_as_uint(a);
    asm("mov.b64 %0, {%1, %1};" : "=l"(r) : "r"(ai));
    return r;
}
__device__ __forceinline__ float2 upk(ull v) {
    union { ull u; float2 f; } c; c.u = v; return c.f;
}

// bf16x2 pack of two floats (v0 -> low half = even K element)
__device__ __forceinline__ u32 packbf(float v0, float v1) {
    __nv_bfloat162 t = __floats2bfloat162_rn(v0, v1);
    u32 r; memcpy(&r, &t, 4); return r;
}

// m16n8k8 row.col bf16 MMA, fp32 accum
__device__ __forceinline__ void mma8(float* c, u32 a0, u32 a1, u32 b) {
    asm("mma.sync.aligned.m16n8k8.row.col.f32.bf16.bf16.f32 "
        "{%0,%1,%2,%3}, {%4,%5}, {%6}, {%0,%1,%2,%3};"
        : "+f"(c[0]), "+f"(c[1]), "+f"(c[2]), "+f"(c[3])
        : "r"(a0), "r"(a1), "r"(b));
}

// ---------------------------------------------------------------------------
// Weight transpose (encoder, OIHW): -> [t][cinpair][cout] bf16x2 hi/lo
// ---------------------------------------------------------------------------
__global__ void wtrans_kernel(const float* __restrict__ w, u32* __restrict__ dst,
                              int Cin, int Cout, int CPG)
{
    const int S = 16 * CPG * Cout;
    int idx = blockIdx.x * 256 + threadIdx.x;
    if (idx >= S) return;
    int co = idx % Cout;
    int rest = idx / Cout;
    int cp = rest % CPG;
    int t  = rest / CPG;
    int ci0 = 2 * cp;
    float v0 = (ci0     < Cin) ? w[((long)co * Cin + ci0    ) * 16 + t] : 0.f;
    float v1 = (ci0 + 1 < Cin) ? w[((long)co * Cin + ci0 + 1) * 16 + t] : 0.f;
    __nv_bfloat162 h = __floats2bfloat162_rn(v0, v1);
    float r0 = v0 - __bfloat162float(h.x);
    float r1 = v1 - __bfloat162float(h.y);
    dst[idx]     = packbf(v0, v1);
    dst[S + idx] = packbf(r0, r1);
}

// ---------------------------------------------------------------------------
// Weight transpose (decoder, torch ConvTranspose layout (Cin, Cout, 4, 4)):
// -> [t][cinpair][coutP] bf16x2 hi/lo, couts zero-padded to CoutP
// ---------------------------------------------------------------------------
__global__ void wtrans_dec_kernel(const float* __restrict__ w, u32* __restrict__ dst,
                                  int Cin, int Cout, int CoutP, int CPG)
{
    const int S = 16 * CPG * CoutP;
    int idx = blockIdx.x * 256 + threadIdx.x;
    if (idx >= S) return;
    int co = idx % CoutP;
    int rest = idx / CoutP;
    int cp = rest % CPG;
    int t  = rest / CPG;
    int ci0 = 2 * cp;
    float v0 = 0.f, v1 = 0.f;
    if (co < Cout) {
        if (ci0     < Cin) v0 = w[((long)ci0       * Cout + co) * 16 + t];
        if (ci0 + 1 < Cin) v1 = w[((long)(ci0 + 1) * Cout + co) * 16 + t];
    }
    __nv_bfloat162 h = __floats2bfloat162_rn(v0, v1);
    float r0 = v0 - __bfloat162float(h.x);
    float r1 = v1 - __bfloat162float(h.y);
    dst[idx]     = packbf(v0, v1);
    dst[S + idx] = packbf(r0, r1);
}

// ---------------------------------------------------------------------------
// Encoder conv via implicit GEMM, split-bf16 m16n8k8 MMA (passing R6 kernel).
// ---------------------------------------------------------------------------
__global__ __launch_bounds__(256)
void conv_enc_mma(const float* __restrict__ in, const u32* __restrict__ wt,
                  const float* __restrict__ bias, float* __restrict__ out,
                  int Cin, int Hin, int Win, int Cout, int CPG)
{
    __shared__ u32 a_s[2][2][10][17][4];
    __shared__ u32 w_sm[2][16][4][72];

    const int Hout = Hin >> 1, Wout = Win >> 1;
    const int tiles_x = Wout >> 4;
    const int tx = blockIdx.x % tiles_x;
    const int ty = blockIdx.x / tiles_x;
    const int OX0 = tx * 16, OY0 = ty * 4;
    const int co0 = blockIdx.y * 64;
    const int b   = blockIdx.z;

    const int tid  = threadIdx.x;
    const int wid  = tid >> 5;
    const int lane = tid & 31;
    const int wm   = wid & 3;
    const int wn   = wid >> 2;
    const int l4   = lane >> 2;
    const int lm4  = lane & 3;

    const u32* wt_lo = wt + 16 * CPG * Cout;

    float acc[4][4];
    #pragma unroll
    for (int nf = 0; nf < 4; nf++)
        #pragma unroll
        for (int c = 0; c < 4; c++) acc[nf][c] = 0.f;

    const long inB = (long)b * Cin * Hin * Win;
    const int nChunk = CPG >> 2;

    #pragma unroll 1
    for (int cic = 0; cic < nChunk; cic++) {
        __syncthreads();
        for (int idx = tid; idx < 10 * 34 * 4; idx += 256) {
            int xs = idx % 34;
            int cp = (idx / 34) & 3;
            int y  = idx / 136;
            int ci0 = cic * 8 + 2 * cp;
            int gy = 2 * OY0 - 1 + y;
            int gx = 2 * OX0 - 1 + xs;
            float v0 = 0.f, v1 = 0.f;
            if (gy >= 0 && gy < Hin && gx >= 0 && gx < Win) {
                if (ci0     < Cin) v0 = in[inB + ((long)ci0       * Hin + gy) * Win + gx];
                if (ci0 + 1 < Cin) v1 = in[inB + ((long)(ci0 + 1) * Hin + gy) * Win + gx];
            }
            __nv_bfloat162 h = __floats2bfloat162_rn(v0, v1);
            float r0 = v0 - __bfloat162float(h.x);
            float r1 = v1 - __bfloat162float(h.y);
            a_s[0][xs & 1][y][xs >> 1][cp] = packbf(v0, v1);
            a_s[1][xs & 1][y][xs >> 1][cp] = packbf(r0, r1);
        }
        for (int idx = tid; idx < 16 * 4 * 64; idx += 256) {
            int co  = idx & 63;
            int cpl = (idx >> 6) & 3;
            int t   = idx >> 8;
            long src = ((long)t * CPG + cic * 4 + cpl) * Cout + co0 + co;
            w_sm[0][t][cpl][co] = wt[src];
            w_sm[1][t][cpl][co] = wt_lo[src];
        }
        __syncthreads();

        #pragma unroll
        for (int ky = 0; ky < 4; ky++) {
            const int y = 2 * wm + ky;
            #pragma unroll
            for (int kx = 0; kx < 4; kx++) {
                const int par = kx & 1;
                const int md  = kx >> 1;
                const int t   = ky * 4 + kx;
                u32 ah0 = a_s[0][par][y][l4 + md][lm4];
                u32 ah1 = a_s[0][par][y][l4 + md + 8][lm4];
                u32 al0 = a_s[1][par][y][l4 + md][lm4];
                u32 al1 = a_s[1][par][y][l4 + md + 8][lm4];
                #pragma unroll
                for (int nf = 0; nf < 4; nf++) {
                    const int coi = wn * 32 + nf * 8 + l4;
                    u32 bh = w_sm[0][t][lm4][coi];
                    u32 bl = w_sm[1][t][lm4][coi];
                    mma8(acc[nf], ah0, ah1, bh);
                    mma8(acc[nf], ah0, ah1, bl);
                    mma8(acc[nf], al0, al1, bh);
                }
            }
        }
    }

    const long outB = (long)b * Cout * Hout * Wout;
    const int oy = OY0 + wm;
    const int ox0l = OX0 + l4;
    #pragma unroll
    for (int nf = 0; nf < 4; nf++) {
        const int cob = co0 + wn * 32 + nf * 8 + 2 * lm4;
        const float b0 = bias[cob], b1 = bias[cob + 1];
        float* o0 = &out[outB + ((long)cob       * Hout + oy) * Wout];
        float* o1 = &out[outB + ((long)(cob + 1) * Hout + oy) * Wout];
        o0[ox0l]     = fmaxf(acc[nf][0] + b0, 0.f);
        o1[ox0l]     = fmaxf(acc[nf][1] + b1, 0.f);
        o0[ox0l + 8] = fmaxf(acc[nf][2] + b0, 0.f);
        o1[ox0l + 8] = fmaxf(acc[nf][3] + b1, 0.f);
    }
}

// ---------------------------------------------------------------------------
// ConvTranspose via implicit GEMM (4 parity sub-convolutions, each a stride-1
// 2x2 conv on the input grid). Block: 8 warps = 2 input rows x 4 parities.
// Warp tile: M = 16 input cols, N = 64 couts (CoutP), K chunked 8 cins.
// ---------------------------------------------------------------------------
__global__ __launch_bounds__(256)
void convt_mma(const float* __restrict__ in, const u32* __restrict__ wt,
               const float* __restrict__ bias, float* __restrict__ out,
               int Cin, int Hin, int Win, int Cout, int CoutP, int CPG)
{
    __shared__ u32 a_s[2][4][18][4];       // [hi/lo][row][col][cp]  2304 B
    __shared__ u32 w_sm[2][16][4][72];     // [hi/lo][t][cp][co]     36864 B

    const int Hout = Hin * 2, Wout = Win * 2;
    const int tiles_x = Win >> 4;
    const int tx = blockIdx.x % tiles_x;
    const int ry = blockIdx.x / tiles_x;
    const int X0 = tx * 16, R0 = ry * 2;
    const int co0 = blockIdx.y * 64;
    const int b   = blockIdx.z;

    const int tid  = threadIdx.x;
    const int wid  = tid >> 5;
    const int lane = tid & 31;
    const int wm   = wid & 1;              // input row within tile
    const int par  = wid >> 1;             // parity class
    const int py   = par & 1;
    const int px   = par >> 1;
    const int l4   = lane >> 2;
    const int lm4  = lane & 3;

    const u32* wt_lo = wt + 16 * CPG * CoutP;

    float acc[8][4];
    #pragma unroll
    for (int nf = 0; nf < 8; nf++)
        #pragma unroll
        for (int c = 0; c < 4; c++) acc[nf][c] = 0.f;

    const long inB = (long)b * Cin * Hin * Win;
    const int nChunk = CPG >> 2;

    #pragma unroll 1
    for (int cic = 0; cic < nChunk; cic++) {
        __syncthreads();
        // ---- stage A patch: rows R0-1..R0+2, cols X0-1..X0+16, 4 cps ----
        for (int idx = tid; idx < 4 * 18 * 4; idx += 256) {
            int cp = idx & 3;
            int c  = (idx >> 2) % 18;
            int r  = idx / 72;
            int ci0 = cic * 8 + 2 * cp;
            int gy = R0 - 1 + r, gx = X0 - 1 + c;
            float v0 = 0.f, v1 = 0.f;
            if (gy >= 0 && gy < Hin && gx >= 0 && gx < Win) {
                if (ci0     < Cin) v0 = in[inB + ((long)ci0       * Hin + gy) * Win + gx];
                if (ci0 + 1 < Cin) v1 = in[inB + ((long)(ci0 + 1) * Hin + gy) * Win + gx];
            }
            __nv_bfloat162 h = __floats2bfloat162_rn(v0, v1);
            float r0 = v0 - __bfloat162float(h.x);
            float r1 = v1 - __bfloat162float(h.y);
            a_s[0][r][c][cp] = packbf(v0, v1);
            a_s[1][r][c][cp] = packbf(r0, r1);
        }
        // ---- stage weights ----
        for (int idx = tid; idx < 16 * 4 * 64; idx += 256) {
            int co  = idx & 63;
            int cpl = (idx >> 6) & 3;
            int t   = idx >> 8;
            long src = ((long)t * CPG + cic * 4 + cpl) * CoutP + co0 + co;
            w_sm[0][t][cpl][co] = wt[src];
            w_sm[1][t][cpl][co] = wt_lo[src];
        }
        __syncthreads();

        // ---- compute: 4 taps (2ky x 2kx for this parity) x 8 nf x 3 mma ----
        #pragma unroll
        for (int kyi = 0; kyi < 2; kyi++) {
            const int pr = wm + 1 + (py == 0 ? -kyi : 1 - kyi);
            const int ky = (1 - py) + 2 * kyi;
            #pragma unroll
            for (int kxi = 0; kxi < 2; kxi++) {
                const int pcb = 1 + (px == 0 ? -kxi : 1 - kxi);
                const int t = ky * 4 + (1 - px) + 2 * kxi;
                u32 ah0 = a_s[0][pr][pcb + l4][lm4];
                u32 ah1 = a_s[0][pr][pcb + l4 + 8][lm4];
                u32 al0 = a_s[1][pr][pcb + l4][lm4];
                u32 al1 = a_s[1][pr][pcb + l4 + 8][lm4];
                #pragma unroll
                for (int nf = 0; nf < 8; nf++) {
                    const int coi = nf * 8 + l4;
                    u32 bh = w_sm[0][t][lm4][coi];
                    u32 bl = w_sm[1][t][lm4][coi];
                    mma8(acc[nf], ah0, ah1, bh);
                    mma8(acc[nf], ah0, ah1, bl);
                    mma8(acc[nf], al0, al1, bh);
                }
            }
        }
    }

    // ---- epilogue: bias + ReLU, write parity outputs ----
    const long outB = (long)b * Cout * Hout * Wout;
    const int oy = 2 * (R0 + wm) + py;
    const int ox = 2 * (X0 + l4) + px;
    #pragma unroll
    for (int nf = 0; nf < 8; nf++) {
        const int cob = co0 + nf * 8 + 2 * lm4;
        if (cob < Cout) {
            const float b0 = bias[cob];
            float* o0 = &out[outB + ((long)cob * Hout + oy) * Wout];
            o0[ox]      = fmaxf(acc[nf][0] + b0, 0.f);
            o0[ox + 16] = fmaxf(acc[nf][2] + b0, 0.f);
        }
        if (cob + 1 < Cout) {
            const float b1 = bias[cob + 1];
            float* o1 = &out[outB + ((long)(cob + 1) * Hout + oy) * Wout];
            o1[ox]      = fmaxf(acc[nf][1] + b1, 0.f);
            o1[ox + 16] = fmaxf(acc[nf][3] + b1, 0.f);
        }
    }
}

// ---------------------------------------------------------------------------
// Final ConvT layer: Cin=32, Cout=3, tanh (scalar).
// ---------------------------------------------------------------------------
__global__ __launch_bounds__(256)
void convt_final_kernel(const float* __restrict__ in, const float* __restrict__ w,
                        const float* __restrict__ bias, float* __restrict__ out)
{
    const int Cin = 32, Hin = 128, Win = 128, Hout = 256, Wout = 256;
    __shared__ float in_s[32][10][11];
    __shared__ float w_s[32][3][16];

    const int tid = threadIdx.x;
    const int b = blockIdx.z;
    const int tx = blockIdx.x & 15;
    const int ty = blockIdx.x >> 4;
    const int oy0 = ty * 16, ox0 = tx * 16;
    const int iyb = oy0 / 2 - 1, ixb = ox0 / 2 - 1;

    for (int i = tid; i < 32 * 3 * 16; i += 256)
        ((float*)w_s)[i] = w[i];
    const float* inb = in + (long)b * Cin * Hin * Win;
    for (int idx = tid; idx < 3200; idx += 256) {
        int c  = idx % 10;
        int r  = (idx / 10) % 10;
        int ci = idx / 100;
        int iy = iyb + r, ix = ixb + c;
        float v = 0.f;
        if (iy >= 0 && iy < Hin && ix >= 0 && ix < Win)
            v = inb[((long)ci * Hin + iy) * Win + ix];
        in_s[ci][r][c] = v;
    }
    __syncthreads();

    const int ox = ox0 + (tid & 15);
    const int oy = oy0 + (tid >> 4);
    const int ky0 = (oy + 1) & 1;
    const int kx0 = (ox + 1) & 1;

    float a0 = bias[0], a1 = bias[1], a2 = bias[2];
    #pragma unroll
    for (int kyi = 0; kyi < 2; kyi++) {
        #pragma unroll
        for (int kxi = 0; kxi < 2; kxi++) {
            const int ky = ky0 + 2 * kyi, kx = kx0 + 2 * kxi;
            const int pr = (oy + 1 - ky) / 2 - iyb;
            const int pc = (ox + 1 - kx) / 2 - ixb;
            const int t = ky * 4 + kx;
            #pragma unroll 8
            for (int ci = 0; ci < 32; ci++) {
                float v = in_s[ci][pr][pc];
                a0 += v * w_s[ci][0][t];
                a1 += v * w_s[ci][1][t];
                a2 += v * w_s[ci][2][t];
            }
        }
    }
    const long o = (long)b * 3 * Hout * Wout + (long)oy * Wout + ox;
    out[o]                    = tanhf(a0);
    out[o + (long)Hout*Wout]  = tanhf(a1);
    out[o + 2L*Hout*Wout]     = tanhf(a2);
}

// ---------------------------------------------------------------------------
// Quantizer
// ---------------------------------------------------------------------------
__global__ void e2_kernel(const float* __restrict__ embed, float* __restrict__ e2)
{
    int k = blockIdx.x * blockDim.x + threadIdx.x;
    if (k >= 1024) return;
    const float* e = embed + (long)k * 512;
    float s = 0.f;
    #pragma unroll 4
    for (int d = 0; d < 512; d++) { float v = e[d]; s += v * v; }
    e2[k] = s;
}

__global__ __launch_bounds__(128)
void argmin_kernel(const float* __restrict__ z, const float* __restrict__ embed,
                   const float* __restrict__ e2, int* __restrict__ idx_out)
{
    __shared__ __align__(16) float z_s[512][8];
    __shared__ float rv[8][128];
    __shared__ int   ri[8][128];
    const int tid = threadIdx.x;
    const int n0 = blockIdx.x * 8;
    const int b = n0 >> 8;
    const int pix0 = n0 & 255;
    const float* zb = z + (long)b * 512 * 256 + pix0;

    for (int i = tid; i < 512 * 8; i += 128) {
        int d = i >> 3, nl = i & 7;
        z_s[d][nl] = zb[(long)d * 256 + nl];
    }
    __syncthreads();

    float bv[8]; int bi[8];
    #pragma unroll
    for (int nl = 0; nl < 8; nl++) { bv[nl] = 3.4e38f; bi[nl] = 0; }

    for (int k = tid; k < 1024; k += 128) {
        const float* e = embed + (long)k * 512;
        ull dp[4];
        #pragma unroll
        for (int h = 0; h < 4; h++) dp[h] = 0ull;
        #pragma unroll 4
        for (int d = 0; d < 512; d++) {
            ull ev2 = pack2(e[d]);
            const ull* zp = reinterpret_cast<const ull*>(&z_s[d][0]);
            ffma2(dp[0], ev2, zp[0]); ffma2(dp[1], ev2, zp[1]);
            ffma2(dp[2], ev2, zp[2]); ffma2(dp[3], ev2, zp[3]);
        }
        float c = e2[k];
        #pragma unroll
        for (int h = 0; h < 4; h++) {
            float2 dv = upk(dp[h]);
            float dist0 = c - 2.f * dv.x;
            float dist1 = c - 2.f * dv.y;
            if (dist0 < bv[2*h])   { bv[2*h]   = dist0; bi[2*h]   = k; }
            if (dist1 < bv[2*h+1]) { bv[2*h+1] = dist1; bi[2*h+1] = k; }
        }
    }
    #pragma unroll
    for (int nl = 0; nl < 8; nl++) { rv[nl][tid] = bv[nl]; ri[nl][tid] = bi[nl]; }
    __syncthreads();
    if (tid < 8) {
        float best = rv[tid][0]; int besti = ri[tid][0];
        for (int j = 1; j < 128; j++) {
            float v = rv[tid][j]; int ii = ri[tid][j];
            if (v < best || (v == best && ii < besti)) { best = v; besti = ii; }
        }
        idx_out[n0 + tid] = besti;
    }
}

__global__ void gather_kernel(const int* __restrict__ idx, const float* __restrict__ embed,
                              float* __restrict__ zq)
{
    const int n = blockIdx.x;
    const int b = n >> 8, pix = n & 255;
    const float* e = embed + (long)idx[n] * 512;
    float* o = zq + (long)b * 512 * 256 + pix;
    for (int d = threadIdx.x; d < 512; d += 256)
        o[(long)d * 256] = e[d];
}

// ---------------------------------------------------------------------------
// Launch
// ---------------------------------------------------------------------------
extern "C" void kernel_launch(void* const* d_in, const int* in_sizes, int n_in,
                              void* d_out, int out_size)
{
    const float* x     = (const float*)d_in[0];
    const float* ew1   = (const float*)d_in[1];
    const float* eb1   = (const float*)d_in[2];
    const float* ew2   = (const float*)d_in[3];
    const float* eb2   = (const float*)d_in[4];
    const float* ew3   = (const float*)d_in[5];
    const float* eb3   = (const float*)d_in[6];
    const float* ew4   = (const float*)d_in[7];
    const float* eb4   = (const float*)d_in[8];
    const float* dw1   = (const float*)d_in[9];
    const float* db1   = (const float*)d_in[10];
    const float* dw2   = (const float*)d_in[11];
    const float* db2   = (const float*)d_in[12];
    const float* dw3   = (const float*)d_in[13];
    const float* db3   = (const float*)d_in[14];
    const float* dw4   = (const float*)d_in[15];
    const float* db4   = (const float*)d_in[16];
    const float* embed = (const float*)d_in[17];
    float* out = (float*)d_out;

    float *A, *B, *e2p; int* idxp; u32* wtp;
    cudaGetSymbolAddress((void**)&A,    g_bufA);
    cudaGetSymbolAddress((void**)&B,    g_bufB);
    cudaGetSymbolAddress((void**)&e2p,  g_e2);
    cudaGetSymbolAddress((void**)&idxp, g_idx);
    cudaGetSymbolAddress((void**)&wtp,  g_wt);

    const int NB = 32;
    // g_wt word offsets
    u32* w1t  = wtp;              // enc1: 2*16*4*64      =    8192
    u32* w2t  = wtp + 8192;       // enc2: 2*16*32*128    =  131072
    u32* w3t  = wtp + 139264;     // enc3: 2*16*64*256    =  524288
    u32* w4t  = wtp + 663552;     // enc4: 2*16*128*512   = 2097152
    u32* dwt1 = wtp + 2760704;    // dec1: 2*16*256*128   = 1048576
    u32* dwt2 = wtp + 3809280;    // dec2: 2*16*64*64     =  131072
    u32* dwt3 = wtp + 3940352;    // dec3: 2*16*32*64(pad)=   65536

    // ---- weight transposes ----
    wtrans_kernel<<<16,   256>>>(ew1, w1t, 3,   64,  4);
    wtrans_kernel<<<256,  256>>>(ew2, w2t, 64,  128, 32);
    wtrans_kernel<<<1024, 256>>>(ew3, w3t, 128, 256, 64);
    wtrans_kernel<<<4096, 256>>>(ew4, w4t, 256, 512, 128);
    wtrans_dec_kernel<<<2048, 256>>>(dw1, dwt1, 512, 128, 128, 256);
    wtrans_dec_kernel<<<256,  256>>>(dw2, dwt2, 128, 64,  64,  64);
    wtrans_dec_kernel<<<128,  256>>>(dw3, dwt3, 64,  32,  64,  32);

    // ---- encoder (tensor-core implicit GEMM) ----
    conv_enc_mma<<<dim3(256, 1, NB), 256>>>(x, w1t, eb1, A, 3,   256, 256, 64,  4);
    conv_enc_mma<<<dim3(64,  2, NB), 256>>>(A, w2t, eb2, B, 64,  128, 128, 128, 32);
    conv_enc_mma<<<dim3(16,  4, NB), 256>>>(B, w3t, eb3, A, 128, 64,  64,  256, 64);
    conv_enc_mma<<<dim3(4,   8, NB), 256>>>(A, w4t, eb4, B, 256, 32,  32,  512, 128);

    // ---- quantizer ----
    e2_kernel<<<4, 256>>>(embed, e2p);
    argmin_kernel<<<1024, 128>>>(B, embed, e2p, idxp);
    gather_kernel<<<8192, 256>>>(idxp, embed, A);          // zq in A

    // ---- decoder (tensor-core implicit GEMM for d1-d3) ----
    // d1: (512,16,16)->(128,32,32): tiles (16/2)*(16/16)=8, couts 2
    convt_mma<<<dim3(8,   2, NB), 256>>>(A, dwt1, db1, B, 512, 16,  16,  128, 128, 256);
    // d2: (128,32,32)->(64,64,64): tiles (32/2)*(32/16)=32, couts 1
    convt_mma<<<dim3(32,  1, NB), 256>>>(B, dwt2, db2, A, 128, 32,  32,  64,  64,  64);
    // d3: (64,64,64)->(32,128,128): tiles (64/2)*(64/16)=128, couts 1 (padded)
    convt_mma<<<dim3(128, 1, NB), 256>>>(A, dwt3, db3, B, 64,  64,  64,  32,  64,  32);
    // d4: (32,128,128)->(3,256,256) + tanh
    convt_final_kernel<<<dim3(256, 1, NB), 256>>>(B, dw4, db4, out);
}